// round 6
// baseline (speedup 1.0000x reference)
#include <cuda_runtime.h>
#include <cstdint>

#define EMB      64
#define CODES    16384
#define NT       1024
#define TT       128
#define NTILES   (NT / TT)    // 8
#define QB       128
#define NTHREADS 512

// packed tf32 B fragments per tile: [split2][ks8][ns16][lane32][2] floats = 16384 floats (64KB)
__device__ float g_B[NTILES][16384];
__device__ float g_hE2[NT];

__device__ __forceinline__ uint32_t f2tf32(float v) {
    uint32_t r;
    asm("cvt.rna.tf32.f32 %0, %1;" : "=r"(r) : "f"(v));
    return r;
}

__device__ __forceinline__ void mma_tf32(float* d, uint4 a, uint2 b) {
    asm volatile(
        "mma.sync.aligned.m16n8k8.row.col.f32.tf32.tf32.f32 "
        "{%0,%1,%2,%3},{%4,%5,%6,%7},{%8,%9},{%0,%1,%2,%3};"
        : "+f"(d[0]), "+f"(d[1]), "+f"(d[2]), "+f"(d[3])
        : "r"(a.x), "r"(a.y), "r"(a.z), "r"(a.w), "r"(b.x), "r"(b.y));
}

#define CP_ASYNC16(dst, src) \
    asm volatile("cp.async.cg.shared.global [%0], [%1], 16;" :: "r"(dst), "l"(src))
#define CP_COMMIT()  asm volatile("cp.async.commit_group;" ::: "memory")
#define CP_WAIT(n)   asm volatile("cp.async.wait_group %0;" :: "n"(n) : "memory")

__device__ __forceinline__ uint32_t smem_u32(const void* p) {
    uint32_t a;
    asm("{ .reg .u64 t; cvta.to.shared.u64 t, %1; cvt.u32.u64 %0, t; }" : "=r"(a) : "l"(p));
    return a;
}

// ---------------- pre-kernel: split E into tf32 hi/lo fragments + halfE2 ----------------
__global__ void pre_kernel(const float* __restrict__ e) {
    const int tile = blockIdx.x;
    const int tid  = threadIdx.x;
    float* base = &g_B[tile][0];

    for (int p = tid; p < 4096; p += blockDim.x) {
        int lane = p & 31;
        int ns   = (p >> 5) & 15;
        int ks   = p >> 9;
        int tok  = tile * TT + ns * 8 + (lane >> 2);
        int k0   = ks * 8 + (lane & 3);
        float v0 = e[(size_t)tok * EMB + k0];
        float v1 = e[(size_t)tok * EMB + k0 + 4];
        uint32_t h0 = f2tf32(v0), h1 = f2tf32(v1);
        float l0 = v0 - __uint_as_float(h0);
        float l1 = v1 - __uint_as_float(h1);
        uint32_t L0 = f2tf32(l0), L1 = f2tf32(l1);
        int off = ks * 1024 + ns * 64 + lane * 2;          // split0
        base[off]     = __uint_as_float(h0);
        base[off + 1] = __uint_as_float(h1);
        base[8192 + off]     = __uint_as_float(L0);        // split1
        base[8192 + off + 1] = __uint_as_float(L1);
    }
    if (tid < TT) {
        int tok = tile * TT + tid;
        const float* row = e + (size_t)tok * EMB;
        float s = 0.f;
#pragma unroll
        for (int k = 0; k < EMB; k++) s += row[k] * row[k];
        g_hE2[tok] = 0.5f * s;
    }
}

// ---------------- SMEM layout (bytes) ----------------
#define SM_A     0          // 65536: [split2][mw4][ms2][ks8][lane32][4]f
#define SM_B0    65536      // 65536 per stage
#define SM_B1    131072
#define SM_HE2   196608     // 4096
#define SM_REDS  200704     // 128*4 floats = 2048
#define SM_REDI  202752     // 128*4 ints   = 2048
#define SM_QIDX  204800     // 128 ints
#define SM_TOTAL 205312

__global__ __launch_bounds__(NTHREADS, 1) void vq_kernel(
    const float* __restrict__ x,      // [B, EMB, CODES]
    const float* __restrict__ e,      // [NT, EMB]
    float* __restrict__ xout,
    float* __restrict__ idxout)
{
    extern __shared__ uint8_t sm[];
    const uint32_t smb = smem_u32(sm);
    const int tid  = threadIdx.x;
    const int warp = tid >> 5;
    const int lane = tid & 31;
    const int mw   = warp >> 2;       // 0..3  (M: rows mw*32 .. +31)
    const int nw   = warp & 3;        // 0..3  (N: tokens nw*32 .. +31 within tile)
    const int b    = blockIdx.y;
    const int c0   = blockIdx.x * QB;

    float* hE2s = (float*)(sm + SM_HE2);
    for (int i = tid; i < NT; i += NTHREADS) hE2s[i] = g_hE2[i];

    // ---- pack A fragments: tf32 hi/lo of x[b][k][c0+r] in per-lane layout ----
    const float* xb = x + (size_t)b * EMB * CODES + c0;
    for (int p = tid; p < 2048; p += NTHREADS) {
        int ln = p & 31;
        int ks = (p >> 5) & 7;
        int ms = (p >> 8) & 1;
        int w  = p >> 9;
        int r  = w * 32 + ms * 16 + (ln >> 2);
        int k0 = ks * 8 + (ln & 3);
        float v00 = xb[(size_t)k0 * CODES + r];            // a0 (r,   k0)
        float v10 = xb[(size_t)k0 * CODES + r + 8];        // a1 (r+8, k0)
        float v01 = xb[(size_t)(k0 + 4) * CODES + r];      // a2 (r,   k0+4)
        float v11 = xb[(size_t)(k0 + 4) * CODES + r + 8];  // a3 (r+8, k0+4)
        uint32_t h0 = f2tf32(v00), h1 = f2tf32(v10), h2 = f2tf32(v01), h3 = f2tf32(v11);
        uint4 hi = {h0, h1, h2, h3};
        uint4 lo = {f2tf32(v00 - __uint_as_float(h0)),
                    f2tf32(v10 - __uint_as_float(h1)),
                    f2tf32(v01 - __uint_as_float(h2)),
                    f2tf32(v11 - __uint_as_float(h3))};
        int off = w * 8192 + ms * 4096 + ks * 512 + ln * 16;   // bytes
        *(uint4*)(sm + SM_A + off)         = hi;
        *(uint4*)(sm + SM_A + 32768 + off) = lo;
    }

    // ---- cp.async prologue: stage tiles 0 and 1 ----
#pragma unroll
    for (int st = 0; st < 2; st++) {
        const char* src = (const char*)&g_B[st][0];
        uint32_t dst = smb + SM_B0 + st * 65536;
#pragma unroll
        for (int it = 0; it < 8; it++) {
            int off = it * NTHREADS * 16 + tid * 16;
            CP_ASYNC16(dst + off, src + off);
        }
        CP_COMMIT();
    }

    float best[4];
    int   bidx[4];
#pragma unroll
    for (int s = 0; s < 4; s++) { best[s] = -3.0e38f; bidx[s] = 0; }

    const int pa[3] = {0, 0, 1};
    const int pb[3] = {0, 1, 0};

    for (int i = 0; i < NTILES; i++) {
        if (i < NTILES - 2) { CP_WAIT(1); } else { CP_WAIT(0); }
        __syncthreads();

        const uint32_t sb = smb + SM_B0 + (uint32_t)(i & 1) * 65536u;
        float acc[32];
#pragma unroll
        for (int z = 0; z < 32; z++) acc[z] = 0.f;

#pragma unroll
        for (int prod = 0; prod < 3; prod++) {
            const uint32_t abase = smb + SM_A + (uint32_t)pa[prod] * 32768u
                                 + (uint32_t)mw * 8192u + (uint32_t)lane * 16u;
            const uint32_t bbase = sb + (uint32_t)pb[prod] * 32768u
                                 + (uint32_t)nw * 1024u + (uint32_t)lane * 8u;
#pragma unroll
            for (int ks = 0; ks < 8; ks++) {
                uint4 a0, a1;
                asm volatile("ld.shared.v4.b32 {%0,%1,%2,%3}, [%4];"
                    : "=r"(a0.x), "=r"(a0.y), "=r"(a0.z), "=r"(a0.w)
                    : "r"(abase + ks * 512u));
                asm volatile("ld.shared.v4.b32 {%0,%1,%2,%3}, [%4];"
                    : "=r"(a1.x), "=r"(a1.y), "=r"(a1.z), "=r"(a1.w)
                    : "r"(abase + 4096u + ks * 512u));
                uint2 bv[4];
#pragma unroll
                for (int n = 0; n < 4; n++) {
                    asm volatile("ld.shared.v2.b32 {%0,%1}, [%2];"
                        : "=r"(bv[n].x), "=r"(bv[n].y)
                        : "r"(bbase + ks * 4096u + n * 256u));
                }
#pragma unroll
                for (int n = 0; n < 4; n++) {
                    mma_tf32(&acc[(0 * 4 + n) * 4], a0, bv[n]);
                    mma_tf32(&acc[(1 * 4 + n) * 4], a1, bv[n]);
                }
            }
        }

        // ---- epilogue: subtract halfE2, running argmax ----
#pragma unroll
        for (int ms = 0; ms < 2; ms++)
#pragma unroll
            for (int n = 0; n < 4; n++) {
                int tokb = i * TT + (nw * 4 + n) * 8 + (lane & 3) * 2;
                const float* d = &acc[(ms * 4 + n) * 4];
#pragma unroll
                for (int j = 0; j < 4; j++) {
                    int tok = tokb + (j & 1);
                    float v = d[j] - hE2s[tok];
                    int s = ms * 2 + (j >> 1);
                    if (v > best[s]) { best[s] = v; bidx[s] = tok; }
                }
            }

        __syncthreads();   // everyone done reading stage before refill
        if (i + 2 < NTILES) {
            const char* src = (const char*)&g_B[i + 2][0];
            uint32_t dst = smb + SM_B0 + (uint32_t)(i & 1) * 65536u;
#pragma unroll
            for (int it = 0; it < 8; it++) {
                int off = it * NTHREADS * 16 + tid * 16;
                CP_ASYNC16(dst + off, src + off);
            }
            CP_COMMIT();
        }
    }

    // ---- merge across the 4 lanes sharing each row (lane^1, lane^2) ----
#pragma unroll
    for (int s = 0; s < 4; s++) {
#pragma unroll
        for (int off = 1; off <= 2; off <<= 1) {
            float os = __shfl_xor_sync(0xffffffffu, best[s], off);
            int   oi = __shfl_xor_sync(0xffffffffu, bidx[s], off);
            if (os > best[s] || (os == best[s] && oi < bidx[s])) {
                best[s] = os; bidx[s] = oi;
            }
        }
    }

    float* REDS = (float*)(sm + SM_REDS);
    int*   REDI = (int*)(sm + SM_REDI);
    int*   QIDX = (int*)(sm + SM_QIDX);
    if ((lane & 3) == 0) {
#pragma unroll
        for (int s = 0; s < 4; s++) {
            int row = mw * 32 + (s >> 1) * 16 + (lane >> 2) + (s & 1) * 8;
            REDS[row * 4 + nw] = best[s];
            REDI[row * 4 + nw] = bidx[s];
        }
    }
    __syncthreads();

    if (tid < QB) {
        float bs = -3.0e38f;
        int   bi = 0x7fffffff;
#pragma unroll
        for (int g = 0; g < 4; g++) {
            float s = REDS[tid * 4 + g];
            int   ii = REDI[tid * 4 + g];
            if (s > bs || (s == bs && ii < bi)) { bs = s; bi = ii; }
        }
        QIDX[tid] = bi;
        idxout[(size_t)b * CODES + c0 + tid] = (float)bi;
    }
    __syncthreads();

    // ---- gather x_out ----
#pragma unroll
    for (int it = 0; it < (EMB * QB) / NTHREADS; ++it) {
        int idx = it * NTHREADS + tid;
        int q = idx & (QB - 1);
        int j = idx >> 7;
        xout[(size_t)b * EMB * CODES + (size_t)j * CODES + c0 + q] =
            e[(size_t)QIDX[q] * EMB + j];
    }
}

extern "C" void kernel_launch(void* const* d_in, const int* in_sizes, int n_in,
                              void* d_out, int out_size) {
    const float* x = (const float*)d_in[0];   // [16, 64, 16384]
    const float* e = (const float*)d_in[1];   // [1024, 64]
    int B = in_sizes[0] / (EMB * CODES);

    float* xout   = (float*)d_out;
    float* idxout = xout + (size_t)B * EMB * CODES;

    pre_kernel<<<NTILES, 256>>>(e);

    cudaFuncSetAttribute(vq_kernel, cudaFuncAttributeMaxDynamicSharedMemorySize, SM_TOTAL);
    dim3 grid(CODES / QB, B);
    vq_kernel<<<grid, NTHREADS, SM_TOTAL>>>(x, e, xout, idxout);
}

// round 7
// speedup vs baseline: 1.1939x; 1.1939x over previous
#include <cuda_runtime.h>
#include <cstdint>

#define EMB      64
#define CODES    16384
#define NT       1024
#define TT       128
#define NTILES   (NT / TT)    // 8
#define QB       128
#define NTHREADS 256

// per tile: products [split2][ks8][pair8][lane32][4]f = 16384 floats,
//           H (folded -halfE2 fragments) [pair8][lane32][2]f = 512 floats @16384,
//           pad to 17408 floats (68KB)
#define TILE_FLOATS 17408
#define STAGE_BYTES (TILE_FLOATS * 4)   // 69632
__device__ float g_B[NTILES][TILE_FLOATS];

__device__ __forceinline__ uint32_t f2tf32(float v) {
    uint32_t r;
    asm("cvt.rna.tf32.f32 %0, %1;" : "=r"(r) : "f"(v));
    return r;
}

__device__ __forceinline__ void mma_tf32(float* d, uint4 a, uint2 b) {
    asm volatile(
        "mma.sync.aligned.m16n8k8.row.col.f32.tf32.tf32.f32 "
        "{%0,%1,%2,%3},{%4,%5,%6,%7},{%8,%9},{%0,%1,%2,%3};"
        : "+f"(d[0]), "+f"(d[1]), "+f"(d[2]), "+f"(d[3])
        : "r"(a.x), "r"(a.y), "r"(a.z), "r"(a.w), "r"(b.x), "r"(b.y));
}

#define CP_ASYNC16(dst, src) \
    asm volatile("cp.async.cg.shared.global [%0], [%1], 16;" :: "r"(dst), "l"(src))
#define CP_COMMIT()  asm volatile("cp.async.commit_group;" ::: "memory")
#define CP_WAIT(n)   asm volatile("cp.async.wait_group %0;" :: "n"(n) : "memory")
#define LDS128(v, addr) \
    asm volatile("ld.shared.v4.b32 {%0,%1,%2,%3}, [%4];" \
        : "=r"((v).x), "=r"((v).y), "=r"((v).z), "=r"((v).w) : "r"(addr))
#define LDS64(v, addr) \
    asm volatile("ld.shared.v2.b32 {%0,%1}, [%2];" \
        : "=r"((v).x), "=r"((v).y) : "r"(addr))

__device__ __forceinline__ uint32_t smem_u32(const void* p) {
    uint32_t a;
    asm("{ .reg .u64 t; cvta.to.shared.u64 t, %1; cvt.u32.u64 %0, t; }" : "=r"(a) : "l"(p));
    return a;
}

// ---------------- pre-kernel: tf32 hi/lo splits of E (paired-n layout) + -h frags ----------------
__global__ void pre_kernel(const float* __restrict__ e) {
    const int tile = blockIdx.x;
    const int tid  = threadIdx.x;
    float* base = &g_B[tile][0];

    // product region: positions ks8 * pair8 * lane32 = 2048 (per split; do both)
    for (int pos = tid; pos < 2048; pos += blockDim.x) {
        int lane = pos & 31;
        int pr   = (pos >> 5) & 7;
        int ks   = pos >> 8;
#pragma unroll
        for (int s = 0; s < 2; s++) {
            int n   = pr * 2 + s;
            int tok = tile * TT + n * 8 + (lane >> 2);
            int k0  = ks * 8 + (lane & 3);
            float v0 = e[(size_t)tok * EMB + k0];       // b0 (k)
            float v1 = e[(size_t)tok * EMB + k0 + 4];   // b1 (k+4)
            uint32_t h0 = f2tf32(v0), h1 = f2tf32(v1);
            uint32_t L0 = f2tf32(v0 - __uint_as_float(h0));
            uint32_t L1 = f2tf32(v1 - __uint_as_float(h1));
            int off = ks * 1024 + pr * 128 + lane * 4 + s * 2;
            base[off]          = __uint_as_float(h0);   // split0 b0
            base[off + 1]      = __uint_as_float(h1);   // split0 b1
            base[8192 + off]     = __uint_as_float(L0); // split1 b0
            base[8192 + off + 1] = __uint_as_float(L1); // split1 b1
        }
    }

    // H region: [pair8][lane32][2] — B fragment of the folded -halfE2 chunk.
    // b0 at (k=lane%4, col=lane/4): k==0 -> tf32hi(-h), k==1 -> tf32lo(-h), else 0.
    for (int idx = tid; idx < 512; idx += blockDim.x) {
        int lane = idx & 31;
        int rest = idx >> 5;        // 0..15
        int p = rest >> 1;
        int s = rest & 1;
        int n = p * 2 + s;
        int tok = tile * TT + n * 8 + (lane >> 2);
        int k = lane & 3;
        float val = 0.f;
        if (k < 2) {
            const float* row = e + (size_t)tok * EMB;
            float h = 0.f;
#pragma unroll
            for (int kk = 0; kk < EMB; kk++) h += row[kk] * row[kk];
            float nh = -0.5f * h;
            uint32_t hh = f2tf32(nh);
            if (k == 0) val = __uint_as_float(hh);
            else        val = __uint_as_float(f2tf32(nh - __uint_as_float(hh)));
        }
        base[16384 + (p * 32 + lane) * 2 + s] = val;
    }
}

// ---------------- SMEM layout (bytes) ----------------
#define SM_A     0                       // 65536: [split2][mw4][ms2][ks8][lane32][4]f
#define SM_B0    65536                   // STAGE_BYTES per stage
#define SM_B1    (SM_B0 + STAGE_BYTES)   // 135168
#define SM_REDS  (SM_B1 + STAGE_BYTES)   // 204800: 128*2 floats
#define SM_REDI  (SM_REDS + 1024)        // 205824: 128*2 ints
#define SM_QIDX  (SM_REDI + 1024)        // 206848: 128 ints
#define SM_TOTAL (SM_QIDX + 512)         // 207360

__global__ __launch_bounds__(NTHREADS, 1) void vq_kernel(
    const float* __restrict__ x,      // [B, EMB, CODES]
    const float* __restrict__ e,      // [NT, EMB]
    float* __restrict__ xout,
    float* __restrict__ idxout)
{
    extern __shared__ uint8_t sm[];
    const uint32_t smb = smem_u32(sm);
    const int tid  = threadIdx.x;
    const int warp = tid >> 5;
    const int lane = tid & 31;
    const int mw   = warp >> 1;       // 0..3 (rows mw*32 .. +31)
    const int nw   = warp & 1;        // 0..1 (tokens nw*64 .. +63 in tile)
    const int b    = blockIdx.y;
    const int c0   = blockIdx.x * QB;

    // ---- pack A fragments: tf32 hi/lo of x[b][k][c0+r], per-lane layout ----
    const float* xb = x + (size_t)b * EMB * CODES + c0;
    for (int p = tid; p < 2048; p += NTHREADS) {
        int ln = p & 31;
        int ks = (p >> 5) & 7;
        int ms = (p >> 8) & 1;
        int w  = p >> 9;
        int r  = w * 32 + ms * 16 + (ln >> 2);
        int k0 = ks * 8 + (ln & 3);
        float v00 = xb[(size_t)k0 * CODES + r];            // a0 (r,   k0)
        float v10 = xb[(size_t)k0 * CODES + r + 8];        // a1 (r+8, k0)
        float v01 = xb[(size_t)(k0 + 4) * CODES + r];      // a2 (r,   k0+4)
        float v11 = xb[(size_t)(k0 + 4) * CODES + r + 8];  // a3 (r+8, k0+4)
        uint32_t h0 = f2tf32(v00), h1 = f2tf32(v10), h2 = f2tf32(v01), h3 = f2tf32(v11);
        uint4 hi = {h0, h1, h2, h3};
        uint4 lo = {f2tf32(v00 - __uint_as_float(h0)),
                    f2tf32(v10 - __uint_as_float(h1)),
                    f2tf32(v01 - __uint_as_float(h2)),
                    f2tf32(v11 - __uint_as_float(h3))};
        int off = w * 8192 + ms * 4096 + ks * 512 + ln * 16;   // bytes
        *(uint4*)(sm + SM_A + off)         = hi;
        *(uint4*)(sm + SM_A + 32768 + off) = lo;
    }

    // ---- cp.async prologue: stage tiles 0 and 1 (17 x 4KB sweeps each) ----
#pragma unroll
    for (int st = 0; st < 2; st++) {
        const char* src = (const char*)&g_B[st][0];
        uint32_t dst = smb + SM_B0 + st * STAGE_BYTES;
#pragma unroll
        for (int it = 0; it < 17; it++) {
            int off = it * NTHREADS * 16 + tid * 16;
            CP_ASYNC16(dst + off, src + off);
        }
        CP_COMMIT();
    }

    float best[4];
    int   bidx[4];
#pragma unroll
    for (int s = 0; s < 4; s++) { best[s] = -3.0e38f; bidx[s] = 0; }

    // constant "ones" A fragment for the -h fold: A[r,k]=1 for k<2
    const uint32_t onec = ((lane & 3) < 2) ? 0x3F800000u : 0u;
    const uint4 aones = {onec, onec, 0u, 0u};

    const uint32_t a0base = smb + SM_A + (uint32_t)mw * 8192u + (uint32_t)lane * 16u;
    const uint32_t a1base = a0base + 32768u;

    for (int i = 0; i < NTILES; i++) {
        if (i < NTILES - 2) { CP_WAIT(1); } else { CP_WAIT(0); }
        __syncthreads();

        const uint32_t sb = smb + SM_B0 + (uint32_t)(i & 1) * STAGE_BYTES;
        const uint32_t bpair = sb + (uint32_t)nw * 2048u + (uint32_t)lane * 16u;
        float acc[64];
#pragma unroll
        for (int z = 0; z < 64; z++) acc[z] = 0.f;

#pragma unroll
        for (int ks = 0; ks < 8; ks++) {
            uint4 ah0m0, ah0m1, ah1m0, ah1m1;
            LDS128(ah0m0, a0base + ks * 512u);
            LDS128(ah0m1, a0base + 4096u + ks * 512u);
            LDS128(ah1m0, a1base + ks * 512u);
            LDS128(ah1m1, a1base + 4096u + ks * 512u);
            uint4 bg0[4], bg1[4];
#pragma unroll
            for (int pp = 0; pp < 4; pp++) {
                LDS128(bg0[pp], bpair + ks * 4096u + pp * 512u);
                LDS128(bg1[pp], bpair + 32768u + ks * 4096u + pp * 512u);
            }
#pragma unroll
            for (int pp = 0; pp < 4; pp++) {
#pragma unroll
                for (int s = 0; s < 2; s++) {
                    int n = pp * 2 + s;
                    uint2 b0 = s ? make_uint2(bg0[pp].z, bg0[pp].w)
                                 : make_uint2(bg0[pp].x, bg0[pp].y);
                    uint2 b1 = s ? make_uint2(bg1[pp].z, bg1[pp].w)
                                 : make_uint2(bg1[pp].x, bg1[pp].y);
                    mma_tf32(&acc[(0 * 8 + n) * 4], ah0m0, b0);   // h0*g0
                    mma_tf32(&acc[(1 * 8 + n) * 4], ah0m1, b0);
                    mma_tf32(&acc[(0 * 8 + n) * 4], ah0m0, b1);   // h0*g1
                    mma_tf32(&acc[(1 * 8 + n) * 4], ah0m1, b1);
                    mma_tf32(&acc[(0 * 8 + n) * 4], ah1m0, b0);   // h1*g0
                    mma_tf32(&acc[(1 * 8 + n) * 4], ah1m1, b0);
                }
            }
        }

        // ---- folded -halfE2 chunk: acc += ones * (-h) ----
        const uint32_t hbase = sb + 65536u + (uint32_t)nw * 1024u + (uint32_t)lane * 8u;
#pragma unroll
        for (int pp = 0; pp < 4; pp++) {
            uint2 hp;
            LDS64(hp, hbase + pp * 256u);
            uint2 bh0 = {hp.x, 0u};
            uint2 bh1 = {hp.y, 0u};
            int n0 = pp * 2, n1 = pp * 2 + 1;
            mma_tf32(&acc[(0 * 8 + n0) * 4], aones, bh0);
            mma_tf32(&acc[(1 * 8 + n0) * 4], aones, bh0);
            mma_tf32(&acc[(0 * 8 + n1) * 4], aones, bh1);
            mma_tf32(&acc[(1 * 8 + n1) * 4], aones, bh1);
        }

        // ---- epilogue: pure register argmax (score already = dot - h) ----
#pragma unroll
        for (int ms = 0; ms < 2; ms++)
#pragma unroll
            for (int n = 0; n < 8; n++) {
                int tokb = i * TT + nw * 64 + n * 8 + (lane & 3) * 2;
                const float* d = &acc[(ms * 8 + n) * 4];
#pragma unroll
                for (int j = 0; j < 4; j++) {
                    int tok = tokb + (j & 1);
                    float v = d[j];
                    int s = ms * 2 + (j >> 1);
                    if (v > best[s]) { best[s] = v; bidx[s] = tok; }
                }
            }

        __syncthreads();   // everyone done reading stage before refill
        if (i + 2 < NTILES) {
            const char* src = (const char*)&g_B[i + 2][0];
            uint32_t dst = smb + SM_B0 + (uint32_t)(i & 1) * STAGE_BYTES;
#pragma unroll
            for (int it = 0; it < 17; it++) {
                int off = it * NTHREADS * 16 + tid * 16;
                CP_ASYNC16(dst + off, src + off);
            }
            CP_COMMIT();
        }
    }

    // ---- merge across the 4 lanes sharing each row (lane^1, lane^2) ----
#pragma unroll
    for (int s = 0; s < 4; s++) {
#pragma unroll
        for (int off = 1; off <= 2; off <<= 1) {
            float os = __shfl_xor_sync(0xffffffffu, best[s], off);
            int   oi = __shfl_xor_sync(0xffffffffu, bidx[s], off);
            if (os > best[s] || (os == best[s] && oi < bidx[s])) {
                best[s] = os; bidx[s] = oi;
            }
        }
    }

    float* REDS = (float*)(sm + SM_REDS);
    int*   REDI = (int*)(sm + SM_REDI);
    int*   QIDX = (int*)(sm + SM_QIDX);
    if ((lane & 3) == 0) {
#pragma unroll
        for (int s = 0; s < 4; s++) {
            int row = mw * 32 + (s >> 1) * 16 + (lane >> 2) + (s & 1) * 8;
            REDS[row * 2 + nw] = best[s];
            REDI[row * 2 + nw] = bidx[s];
        }
    }
    __syncthreads();

    if (tid < QB) {
        float s0 = REDS[tid * 2], s1 = REDS[tid * 2 + 1];
        int   i0 = REDI[tid * 2], i1 = REDI[tid * 2 + 1];
        int bi = (s1 > s0 || (s1 == s0 && i1 < i0)) ? i1 : i0;
        QIDX[tid] = bi;
        idxout[(size_t)b * CODES + c0 + tid] = (float)bi;
    }
    __syncthreads();

    // ---- gather x_out ----
#pragma unroll
    for (int it = 0; it < (EMB * QB) / NTHREADS; ++it) {
        int idx = it * NTHREADS + tid;
        int q = idx & (QB - 1);
        int j = idx >> 7;
        xout[(size_t)b * EMB * CODES + (size_t)j * CODES + c0 + q] =
            e[(size_t)QIDX[q] * EMB + j];
    }
}

extern "C" void kernel_launch(void* const* d_in, const int* in_sizes, int n_in,
                              void* d_out, int out_size) {
    const float* x = (const float*)d_in[0];   // [16, 64, 16384]
    const float* e = (const float*)d_in[1];   // [1024, 64]
    int B = in_sizes[0] / (EMB * CODES);

    float* xout   = (float*)d_out;
    float* idxout = xout + (size_t)B * EMB * CODES;

    pre_kernel<<<NTILES, 256>>>(e);

    cudaFuncSetAttribute(vq_kernel, cudaFuncAttributeMaxDynamicSharedMemorySize, SM_TOTAL);
    dim3 grid(CODES / QB, B);
    vq_kernel<<<grid, NTHREADS, SM_TOTAL>>>(x, e, xout, idxout);
}

// round 8
// speedup vs baseline: 1.2022x; 1.0070x over previous
#include <cuda_runtime.h>
#include <cstdint>

#define EMB      64
#define CODES    16384
#define NT       1024
#define TT       128
#define NTILES   (NT / TT)    // 8
#define QB       128
#define NTHREADS 256

// per tile: products [split2][ks8][pair8][lane32][4]f = 16384 floats,
//           H (folded -halfE2 fragments) [pair8][lane32][2]f = 512 floats @16384,
//           pad to 17408 floats (68KB)
#define TILE_FLOATS 17408
#define STAGE_BYTES (TILE_FLOATS * 4)   // 69632
__device__ float g_B[NTILES][TILE_FLOATS];

__device__ __forceinline__ uint32_t f2tf32(float v) {
    uint32_t r;
    asm("cvt.rna.tf32.f32 %0, %1;" : "=r"(r) : "f"(v));
    return r;
}

__device__ __forceinline__ void mma_tf32(float* d, uint4 a, uint2 b) {
    asm volatile(
        "mma.sync.aligned.m16n8k8.row.col.f32.tf32.tf32.f32 "
        "{%0,%1,%2,%3},{%4,%5,%6,%7},{%8,%9},{%0,%1,%2,%3};"
        : "+f"(d[0]), "+f"(d[1]), "+f"(d[2]), "+f"(d[3])
        : "r"(a.x), "r"(a.y), "r"(a.z), "r"(a.w), "r"(b.x), "r"(b.y));
}

#define CP_ASYNC16(dst, src) \
    asm volatile("cp.async.cg.shared.global [%0], [%1], 16;" :: "r"(dst), "l"(src))
#define CP_COMMIT()  asm volatile("cp.async.commit_group;" ::: "memory")
#define CP_WAIT(n)   asm volatile("cp.async.wait_group %0;" :: "n"(n) : "memory")
#define LDS128(v, addr) \
    asm volatile("ld.shared.v4.b32 {%0,%1,%2,%3}, [%4];" \
        : "=r"((v).x), "=r"((v).y), "=r"((v).z), "=r"((v).w) : "r"(addr))
#define LDS64(v, addr) \
    asm volatile("ld.shared.v2.b32 {%0,%1}, [%2];" \
        : "=r"((v).x), "=r"((v).y) : "r"(addr))

__device__ __forceinline__ uint32_t smem_u32(const void* p) {
    uint32_t a;
    asm("{ .reg .u64 t; cvta.to.shared.u64 t, %1; cvt.u32.u64 %0, t; }" : "=r"(a) : "l"(p));
    return a;
}

// ---------------- pre-kernel: tf32 hi/lo splits of E (paired-n layout) + -h frags ----------------
__global__ void pre_kernel(const float* __restrict__ e) {
    const int tile = blockIdx.x;
    const int tid  = threadIdx.x;
    float* base = &g_B[tile][0];

    for (int pos = tid; pos < 2048; pos += blockDim.x) {
        int lane = pos & 31;
        int pr   = (pos >> 5) & 7;
        int ks   = pos >> 8;
#pragma unroll
        for (int s = 0; s < 2; s++) {
            int n   = pr * 2 + s;
            int tok = tile * TT + n * 8 + (lane >> 2);
            int k0  = ks * 8 + (lane & 3);
            float v0 = e[(size_t)tok * EMB + k0];       // b0 (k)
            float v1 = e[(size_t)tok * EMB + k0 + 4];   // b1 (k+4)
            uint32_t h0 = f2tf32(v0), h1 = f2tf32(v1);
            uint32_t L0 = f2tf32(v0 - __uint_as_float(h0));
            uint32_t L1 = f2tf32(v1 - __uint_as_float(h1));
            int off = ks * 1024 + pr * 128 + lane * 4 + s * 2;
            base[off]          = __uint_as_float(h0);   // split0 b0
            base[off + 1]      = __uint_as_float(h1);   // split0 b1
            base[8192 + off]     = __uint_as_float(L0); // split1 b0
            base[8192 + off + 1] = __uint_as_float(L1); // split1 b1
        }
    }

    // H region: [pair8][lane32][2] — B fragment of the folded -halfE2 chunk.
    for (int idx = tid; idx < 512; idx += blockDim.x) {
        int lane = idx & 31;
        int rest = idx >> 5;        // 0..15
        int p = rest >> 1;
        int s = rest & 1;
        int n = p * 2 + s;
        int tok = tile * TT + n * 8 + (lane >> 2);
        int k = lane & 3;
        float val = 0.f;
        if (k < 2) {
            const float* row = e + (size_t)tok * EMB;
            float h = 0.f;
#pragma unroll
            for (int kk = 0; kk < EMB; kk++) h += row[kk] * row[kk];
            float nh = -0.5f * h;
            uint32_t hh = f2tf32(nh);
            if (k == 0) val = __uint_as_float(hh);
            else        val = __uint_as_float(f2tf32(nh - __uint_as_float(hh)));
        }
        base[16384 + (p * 32 + lane) * 2 + s] = val;
    }
}

// ---------------- SMEM layout (bytes) ----------------
#define SM_A     0                       // 65536: [split2][mw4][ms2][ks8][lane32][4]f
#define SM_B0    65536                   // STAGE_BYTES per stage
#define SM_B1    (SM_B0 + STAGE_BYTES)   // 135168
#define SM_REDS  (SM_B1 + STAGE_BYTES)   // 204800: 128*2 floats
#define SM_REDI  (SM_REDS + 1024)        // 205824
#define SM_QIDX  (SM_REDI + 1024)        // 206848
#define SM_TOTAL (SM_QIDX + 512)         // 207360

__global__ __launch_bounds__(NTHREADS, 1) void vq_kernel(
    const float* __restrict__ x,      // [B, EMB, CODES]
    const float* __restrict__ e,      // [NT, EMB]
    float* __restrict__ xout,
    float* __restrict__ idxout)
{
    extern __shared__ uint8_t sm[];
    const uint32_t smb = smem_u32(sm);
    const int tid  = threadIdx.x;
    const int warp = tid >> 5;
    const int lane = tid & 31;
    const int mw   = warp >> 1;       // 0..3 (rows mw*32 .. +31)
    const int nw   = warp & 1;        // 0..1 (tokens nw*64 .. +63 in tile)
    const int b    = blockIdx.y;
    const int c0   = blockIdx.x * QB;

    // ---- pack A fragments: tf32 hi/lo of x[b][k][c0+r], per-lane layout ----
    const float* xb = x + (size_t)b * EMB * CODES + c0;
    for (int p = tid; p < 2048; p += NTHREADS) {
        int ln = p & 31;
        int ks = (p >> 5) & 7;
        int ms = (p >> 8) & 1;
        int w  = p >> 9;
        int r  = w * 32 + ms * 16 + (ln >> 2);
        int k0 = ks * 8 + (ln & 3);
        float v00 = xb[(size_t)k0 * CODES + r];
        float v10 = xb[(size_t)k0 * CODES + r + 8];
        float v01 = xb[(size_t)(k0 + 4) * CODES + r];
        float v11 = xb[(size_t)(k0 + 4) * CODES + r + 8];
        uint32_t h0 = f2tf32(v00), h1 = f2tf32(v10), h2 = f2tf32(v01), h3 = f2tf32(v11);
        uint4 hi = {h0, h1, h2, h3};
        uint4 lo = {f2tf32(v00 - __uint_as_float(h0)),
                    f2tf32(v10 - __uint_as_float(h1)),
                    f2tf32(v01 - __uint_as_float(h2)),
                    f2tf32(v11 - __uint_as_float(h3))};
        int off = w * 8192 + ms * 4096 + ks * 512 + ln * 16;   // bytes
        *(uint4*)(sm + SM_A + off)         = hi;
        *(uint4*)(sm + SM_A + 32768 + off) = lo;
    }

    // ---- cp.async prologue: stage tiles 0 and 1 ----
#pragma unroll
    for (int st = 0; st < 2; st++) {
        const char* src = (const char*)&g_B[st][0];
        uint32_t dst = smb + SM_B0 + st * STAGE_BYTES;
#pragma unroll
        for (int it = 0; it < 17; it++) {
            int off = it * NTHREADS * 16 + tid * 16;
            CP_ASYNC16(dst + off, src + off);
        }
        CP_COMMIT();
    }

    float best[4];
    int   bidx[4];
#pragma unroll
    for (int s = 0; s < 4; s++) { best[s] = -3.0e38f; bidx[s] = 0; }

    // constant "ones" A fragment for the -h fold
    const uint32_t onec = ((lane & 3) < 2) ? 0x3F800000u : 0u;
    const uint4 aones = {onec, onec, 0u, 0u};

    const uint32_t a0base = smb + SM_A + (uint32_t)mw * 8192u + (uint32_t)lane * 16u;
    const uint32_t a1base = a0base + 32768u;

    for (int i = 0; i < NTILES; i++) {
        if (i < NTILES - 2) { CP_WAIT(1); } else { CP_WAIT(0); }
        __syncthreads();

        const uint32_t sb = smb + SM_B0 + (uint32_t)(i & 1) * STAGE_BYTES;
        const uint32_t bpair = sb + (uint32_t)nw * 2048u + (uint32_t)lane * 16u;
        float acc[64];
#pragma unroll
        for (int z = 0; z < 64; z++) acc[z] = 0.f;

        // ---- software-pipelined ks loop: prefetch ks+1 frags during ks HMMAs ----
        uint4 cA[4], cB0[4], cB1[4];     // current fragments
        LDS128(cA[0], a0base);
        LDS128(cA[1], a0base + 4096u);
        LDS128(cA[2], a1base);
        LDS128(cA[3], a1base + 4096u);
#pragma unroll
        for (int pp = 0; pp < 4; pp++) {
            LDS128(cB0[pp], bpair + pp * 512u);
            LDS128(cB1[pp], bpair + 32768u + pp * 512u);
        }

#pragma unroll
        for (int ks = 0; ks < 8; ks++) {
            uint4 nA[4], nB0[4], nB1[4];
            if (ks < 7) {
                LDS128(nA[0], a0base + (ks + 1) * 512u);
                LDS128(nA[1], a0base + 4096u + (ks + 1) * 512u);
                LDS128(nA[2], a1base + (ks + 1) * 512u);
                LDS128(nA[3], a1base + 4096u + (ks + 1) * 512u);
#pragma unroll
                for (int pp = 0; pp < 4; pp++) {
                    LDS128(nB0[pp], bpair + (ks + 1) * 4096u + pp * 512u);
                    LDS128(nB1[pp], bpair + 32768u + (ks + 1) * 4096u + pp * 512u);
                }
            }

            // product-major HMMA ordering: 3 passes x 16 independent (m,n) chains
#pragma unroll
            for (int pp = 0; pp < 4; pp++) {        // pass 0: h0*g0
#pragma unroll
                for (int s = 0; s < 2; s++) {
                    int n = pp * 2 + s;
                    uint2 b0 = s ? make_uint2(cB0[pp].z, cB0[pp].w)
                                 : make_uint2(cB0[pp].x, cB0[pp].y);
                    mma_tf32(&acc[(0 * 8 + n) * 4], cA[0], b0);
                    mma_tf32(&acc[(1 * 8 + n) * 4], cA[1], b0);
                }
            }
#pragma unroll
            for (int pp = 0; pp < 4; pp++) {        // pass 1: h0*g1
#pragma unroll
                for (int s = 0; s < 2; s++) {
                    int n = pp * 2 + s;
                    uint2 b1 = s ? make_uint2(cB1[pp].z, cB1[pp].w)
                                 : make_uint2(cB1[pp].x, cB1[pp].y);
                    mma_tf32(&acc[(0 * 8 + n) * 4], cA[0], b1);
                    mma_tf32(&acc[(1 * 8 + n) * 4], cA[1], b1);
                }
            }
#pragma unroll
            for (int pp = 0; pp < 4; pp++) {        // pass 2: h1*g0
#pragma unroll
                for (int s = 0; s < 2; s++) {
                    int n = pp * 2 + s;
                    uint2 b0 = s ? make_uint2(cB0[pp].z, cB0[pp].w)
                                 : make_uint2(cB0[pp].x, cB0[pp].y);
                    mma_tf32(&acc[(0 * 8 + n) * 4], cA[2], b0);
                    mma_tf32(&acc[(1 * 8 + n) * 4], cA[3], b0);
                }
            }

            if (ks < 7) {
#pragma unroll
                for (int z = 0; z < 4; z++) { cA[z] = nA[z]; cB0[z] = nB0[z]; cB1[z] = nB1[z]; }
            }
        }

        // ---- folded -halfE2 chunk: acc += ones * (-h) ----
        const uint32_t hbase = sb + 65536u + (uint32_t)nw * 1024u + (uint32_t)lane * 8u;
#pragma unroll
        for (int pp = 0; pp < 4; pp++) {
            uint2 hp;
            LDS64(hp, hbase + pp * 256u);
            uint2 bh0 = {hp.x, 0u};
            uint2 bh1 = {hp.y, 0u};
            int n0 = pp * 2, n1 = pp * 2 + 1;
            mma_tf32(&acc[(0 * 8 + n0) * 4], aones, bh0);
            mma_tf32(&acc[(1 * 8 + n0) * 4], aones, bh0);
            mma_tf32(&acc[(0 * 8 + n1) * 4], aones, bh1);
            mma_tf32(&acc[(1 * 8 + n1) * 4], aones, bh1);
        }

        // ---- epilogue: pure register argmax ----
#pragma unroll
        for (int ms = 0; ms < 2; ms++)
#pragma unroll
            for (int n = 0; n < 8; n++) {
                int tokb = i * TT + nw * 64 + n * 8 + (lane & 3) * 2;
                const float* d = &acc[(ms * 8 + n) * 4];
#pragma unroll
                for (int j = 0; j < 4; j++) {
                    int tok = tokb + (j & 1);
                    float v = d[j];
                    int s = ms * 2 + (j >> 1);
                    if (v > best[s]) { best[s] = v; bidx[s] = tok; }
                }
            }

        __syncthreads();   // everyone done reading stage before refill
        if (i + 2 < NTILES) {
            const char* src = (const char*)&g_B[i + 2][0];
            uint32_t dst = smb + SM_B0 + (uint32_t)(i & 1) * STAGE_BYTES;
#pragma unroll
            for (int it = 0; it < 17; it++) {
                int off = it * NTHREADS * 16 + tid * 16;
                CP_ASYNC16(dst + off, src + off);
            }
            CP_COMMIT();
        }
    }

    // ---- merge across the 4 lanes sharing each row ----
#pragma unroll
    for (int s = 0; s < 4; s++) {
#pragma unroll
        for (int off = 1; off <= 2; off <<= 1) {
            float os = __shfl_xor_sync(0xffffffffu, best[s], off);
            int   oi = __shfl_xor_sync(0xffffffffu, bidx[s], off);
            if (os > best[s] || (os == best[s] && oi < bidx[s])) {
                best[s] = os; bidx[s] = oi;
            }
        }
    }

    float* REDS = (float*)(sm + SM_REDS);
    int*   REDI = (int*)(sm + SM_REDI);
    int*   QIDX = (int*)(sm + SM_QIDX);
    if ((lane & 3) == 0) {
#pragma unroll
        for (int s = 0; s < 4; s++) {
            int row = mw * 32 + (s >> 1) * 16 + (lane >> 2) + (s & 1) * 8;
            REDS[row * 2 + nw] = best[s];
            REDI[row * 2 + nw] = bidx[s];
        }
    }
    __syncthreads();

    if (tid < QB) {
        float s0 = REDS[tid * 2], s1 = REDS[tid * 2 + 1];
        int   i0 = REDI[tid * 2], i1 = REDI[tid * 2 + 1];
        int bi = (s1 > s0 || (s1 == s0 && i1 < i0)) ? i1 : i0;
        QIDX[tid] = bi;
        idxout[(size_t)b * CODES + c0 + tid] = (float)bi;
    }
    __syncthreads();

    // ---- gather x_out ----
#pragma unroll
    for (int it = 0; it < (EMB * QB) / NTHREADS; ++it) {
        int idx = it * NTHREADS + tid;
        int q = idx & (QB - 1);
        int j = idx >> 7;
        xout[(size_t)b * EMB * CODES + (size_t)j * CODES + c0 + q] =
            e[(size_t)QIDX[q] * EMB + j];
    }
}

extern "C" void kernel_launch(void* const* d_in, const int* in_sizes, int n_in,
                              void* d_out, int out_size) {
    const float* x = (const float*)d_in[0];   // [16, 64, 16384]
    const float* e = (const float*)d_in[1];   // [1024, 64]
    int B = in_sizes[0] / (EMB * CODES);

    float* xout   = (float*)d_out;
    float* idxout = xout + (size_t)B * EMB * CODES;

    pre_kernel<<<NTILES, 256>>>(e);

    cudaFuncSetAttribute(vq_kernel, cudaFuncAttributeMaxDynamicSharedMemorySize, SM_TOTAL);
    dim3 grid(CODES / QB, B);
    vq_kernel<<<grid, NTHREADS, SM_TOTAL>>>(x, e, xout, idxout);
}

// round 9
// speedup vs baseline: 1.2092x; 1.0058x over previous
#include <cuda_runtime.h>
#include <cstdint>

#define EMB      64
#define CODES    16384
#define NT       1024
#define TT       128
#define NTILES   (NT / TT)    // 8
#define QB       128
#define NTHREADS 256

#define TILE_FLOATS 17408
#define STAGE_BYTES (TILE_FLOATS * 4)   // 69632
__device__ float g_B[NTILES][TILE_FLOATS];

__device__ __forceinline__ uint32_t f2tf32(float v) {
    uint32_t r;
    asm("cvt.rna.tf32.f32 %0, %1;" : "=r"(r) : "f"(v));
    return r;
}

__device__ __forceinline__ void mma_tf32(float* d, uint4 a, uint2 b) {
    asm volatile(
        "mma.sync.aligned.m16n8k8.row.col.f32.tf32.tf32.f32 "
        "{%0,%1,%2,%3},{%4,%5,%6,%7},{%8,%9},{%0,%1,%2,%3};"
        : "+f"(d[0]), "+f"(d[1]), "+f"(d[2]), "+f"(d[3])
        : "r"(a.x), "r"(a.y), "r"(a.z), "r"(a.w), "r"(b.x), "r"(b.y));
}

#define CP_ASYNC16(dst, src) \
    asm volatile("cp.async.cg.shared.global [%0], [%1], 16;" :: "r"(dst), "l"(src))
#define CP_COMMIT()  asm volatile("cp.async.commit_group;" ::: "memory")
#define CP_WAIT(n)   asm volatile("cp.async.wait_group %0;" :: "n"(n) : "memory")
#define LDS128(v, addr) \
    asm volatile("ld.shared.v4.b32 {%0,%1,%2,%3}, [%4];" \
        : "=r"((v).x), "=r"((v).y), "=r"((v).z), "=r"((v).w) : "r"(addr))
#define LDS64(v, addr) \
    asm volatile("ld.shared.v2.b32 {%0,%1}, [%2];" \
        : "=r"((v).x), "=r"((v).y) : "r"(addr))

__device__ __forceinline__ uint32_t smem_u32(const void* p) {
    uint32_t a;
    asm("{ .reg .u64 t; cvta.to.shared.u64 t, %1; cvt.u32.u64 %0, t; }" : "=r"(a) : "l"(p));
    return a;
}

// ---------------- pre-kernel: tf32 hi/lo splits of E (paired-n layout) + -h frags ----------------
__global__ void pre_kernel(const float* __restrict__ e) {
    const int tile = blockIdx.x;
    const int tid  = threadIdx.x;
    float* base = &g_B[tile][0];

    for (int pos = tid; pos < 2048; pos += blockDim.x) {
        int lane = pos & 31;
        int pr   = (pos >> 5) & 7;
        int ks   = pos >> 8;
#pragma unroll
        for (int s = 0; s < 2; s++) {
            int n   = pr * 2 + s;
            int tok = tile * TT + n * 8 + (lane >> 2);
            int k0  = ks * 8 + (lane & 3);
            float v0 = e[(size_t)tok * EMB + k0];
            float v1 = e[(size_t)tok * EMB + k0 + 4];
            uint32_t h0 = f2tf32(v0), h1 = f2tf32(v1);
            uint32_t L0 = f2tf32(v0 - __uint_as_float(h0));
            uint32_t L1 = f2tf32(v1 - __uint_as_float(h1));
            int off = ks * 1024 + pr * 128 + lane * 4 + s * 2;
            base[off]          = __uint_as_float(h0);
            base[off + 1]      = __uint_as_float(h1);
            base[8192 + off]     = __uint_as_float(L0);
            base[8192 + off + 1] = __uint_as_float(L1);
        }
    }

    // H region: [pair8][lane32][2] — B fragment of folded -halfE2 chunk.
    for (int idx = tid; idx < 512; idx += blockDim.x) {
        int lane = idx & 31;
        int rest = idx >> 5;
        int p = rest >> 1;
        int s = rest & 1;
        int n = p * 2 + s;
        int tok = tile * TT + n * 8 + (lane >> 2);
        int k = lane & 3;
        float val = 0.f;
        if (k < 2) {
            const float* row = e + (size_t)tok * EMB;
            float h = 0.f;
#pragma unroll
            for (int kk = 0; kk < EMB; kk++) h += row[kk] * row[kk];
            float nh = -0.5f * h;
            uint32_t hh = f2tf32(nh);
            if (k == 0) val = __uint_as_float(hh);
            else        val = __uint_as_float(f2tf32(nh - __uint_as_float(hh)));
        }
        base[16384 + (p * 32 + lane) * 2 + s] = val;
    }
}

// ---------------- SMEM layout (bytes) ----------------
#define SM_A     0
#define SM_B0    65536
#define SM_B1    (SM_B0 + STAGE_BYTES)
#define SM_REDS  (SM_B1 + STAGE_BYTES)
#define SM_REDI  (SM_REDS + 1024)
#define SM_QIDX  (SM_REDI + 1024)
#define SM_TOTAL (SM_QIDX + 512)

// ---- mainloop building blocks (exact instruction order via asm volatile) ----
#define LOAD_A(A, ksn) \
    LDS128(A[0], a0base + (ksn) * 512u); \
    LDS128(A[1], a0base + 4096u + (ksn) * 512u); \
    LDS128(A[2], a1base + (ksn) * 512u); \
    LDS128(A[3], a1base + 4096u + (ksn) * 512u)

#define LOAD_B(B0, B1, ksn) \
    LDS128(B0[0], bpair + (ksn) * 4096u); \
    LDS128(B0[1], bpair + (ksn) * 4096u + 512u); \
    LDS128(B0[2], bpair + (ksn) * 4096u + 1024u); \
    LDS128(B0[3], bpair + (ksn) * 4096u + 1536u); \
    LDS128(B1[0], bpair + 32768u + (ksn) * 4096u); \
    LDS128(B1[1], bpair + 32768u + (ksn) * 4096u + 512u); \
    LDS128(B1[2], bpair + 32768u + (ksn) * 4096u + 1024u); \
    LDS128(B1[3], bpair + 32768u + (ksn) * 4096u + 1536u)

#define PASSX(Alo, Ahi, B) do { \
    uint2 _b; \
    _b = make_uint2(B[0].x, B[0].y); mma_tf32(&acc[0],  Alo, _b); mma_tf32(&acc[32], Ahi, _b); \
    _b = make_uint2(B[0].z, B[0].w); mma_tf32(&acc[4],  Alo, _b); mma_tf32(&acc[36], Ahi, _b); \
    _b = make_uint2(B[1].x, B[1].y); mma_tf32(&acc[8],  Alo, _b); mma_tf32(&acc[40], Ahi, _b); \
    _b = make_uint2(B[1].z, B[1].w); mma_tf32(&acc[12], Alo, _b); mma_tf32(&acc[44], Ahi, _b); \
    _b = make_uint2(B[2].x, B[2].y); mma_tf32(&acc[16], Alo, _b); mma_tf32(&acc[48], Ahi, _b); \
    _b = make_uint2(B[2].z, B[2].w); mma_tf32(&acc[20], Alo, _b); mma_tf32(&acc[52], Ahi, _b); \
    _b = make_uint2(B[3].x, B[3].y); mma_tf32(&acc[24], Alo, _b); mma_tf32(&acc[56], Ahi, _b); \
    _b = make_uint2(B[3].z, B[3].w); mma_tf32(&acc[28], Alo, _b); mma_tf32(&acc[60], Ahi, _b); \
} while (0)

// compute on (A,B0,B1); prefetch ks=KSN into (An,B0n,B1n), interleaved between passes
#define STEP(A, B0, B1, An, B0n, B1n, KSN) \
    PASSX(A[0], A[1], B0); \
    LOAD_A(An, KSN); \
    PASSX(A[0], A[1], B1); \
    LOAD_B(B0n, B1n, KSN); \
    PASSX(A[2], A[3], B0)

#define STEP_LAST(A, B0, B1) \
    PASSX(A[0], A[1], B0); \
    PASSX(A[0], A[1], B1); \
    PASSX(A[2], A[3], B0)

__global__ __launch_bounds__(NTHREADS, 1) void vq_kernel(
    const float* __restrict__ x,      // [B, EMB, CODES]
    const float* __restrict__ e,      // [NT, EMB]
    float* __restrict__ xout,
    float* __restrict__ idxout)
{
    extern __shared__ uint8_t sm[];
    const uint32_t smb = smem_u32(sm);
    const int tid  = threadIdx.x;
    const int warp = tid >> 5;
    const int lane = tid & 31;
    const int mw   = warp >> 1;
    const int nw   = warp & 1;
    const int b    = blockIdx.y;
    const int c0   = blockIdx.x * QB;

    // ---- pack A fragments: tf32 hi/lo of x[b][k][c0+r], per-lane layout ----
    const float* xb = x + (size_t)b * EMB * CODES + c0;
    for (int p = tid; p < 2048; p += NTHREADS) {
        int ln = p & 31;
        int ks = (p >> 5) & 7;
        int ms = (p >> 8) & 1;
        int w  = p >> 9;
        int r  = w * 32 + ms * 16 + (ln >> 2);
        int k0 = ks * 8 + (ln & 3);
        float v00 = xb[(size_t)k0 * CODES + r];
        float v10 = xb[(size_t)k0 * CODES + r + 8];
        float v01 = xb[(size_t)(k0 + 4) * CODES + r];
        float v11 = xb[(size_t)(k0 + 4) * CODES + r + 8];
        uint32_t h0 = f2tf32(v00), h1 = f2tf32(v10), h2 = f2tf32(v01), h3 = f2tf32(v11);
        uint4 hi = {h0, h1, h2, h3};
        uint4 lo = {f2tf32(v00 - __uint_as_float(h0)),
                    f2tf32(v10 - __uint_as_float(h1)),
                    f2tf32(v01 - __uint_as_float(h2)),
                    f2tf32(v11 - __uint_as_float(h3))};
        int off = w * 8192 + ms * 4096 + ks * 512 + ln * 16;
        *(uint4*)(sm + SM_A + off)         = hi;
        *(uint4*)(sm + SM_A + 32768 + off) = lo;
    }

    // ---- cp.async prologue: stage tiles 0 and 1 ----
#pragma unroll
    for (int st = 0; st < 2; st++) {
        const char* src = (const char*)&g_B[st][0];
        uint32_t dst = smb + SM_B0 + st * STAGE_BYTES;
#pragma unroll
        for (int it = 0; it < 17; it++) {
            int off = it * NTHREADS * 16 + tid * 16;
            CP_ASYNC16(dst + off, src + off);
        }
        CP_COMMIT();
    }

    float best[4];
    int   bidx[4];
#pragma unroll
    for (int s = 0; s < 4; s++) { best[s] = -3.0e38f; bidx[s] = 0; }

    const uint32_t onec = ((lane & 3) < 2) ? 0x3F800000u : 0u;
    const uint4 aones = {onec, onec, 0u, 0u};

    const uint32_t a0base = smb + SM_A + (uint32_t)mw * 8192u + (uint32_t)lane * 16u;
    const uint32_t a1base = a0base + 32768u;

    for (int i = 0; i < NTILES; i++) {
        if (i < NTILES - 2) { CP_WAIT(1); } else { CP_WAIT(0); }
        __syncthreads();

        const uint32_t sb = smb + SM_B0 + (uint32_t)(i & 1) * STAGE_BYTES;
        const uint32_t bpair = sb + (uint32_t)nw * 2048u + (uint32_t)lane * 16u;
        float acc[64];
#pragma unroll
        for (int z = 0; z < 64; z++) acc[z] = 0.f;

        // ---- copy-free ping-pong mainloop, loads threaded between HMMA passes ----
        uint4 Xa[4], Ya[4], Za[4];   // buffer set a
        uint4 Xb[4], Yb[4], Zb[4];   // buffer set b
        LOAD_A(Xa, 0);
        LOAD_B(Ya, Za, 0);
        STEP(Xa, Ya, Za, Xb, Yb, Zb, 1);   // ks=0
        STEP(Xb, Yb, Zb, Xa, Ya, Za, 2);   // ks=1
        STEP(Xa, Ya, Za, Xb, Yb, Zb, 3);   // ks=2
        STEP(Xb, Yb, Zb, Xa, Ya, Za, 4);   // ks=3
        STEP(Xa, Ya, Za, Xb, Yb, Zb, 5);   // ks=4
        STEP(Xb, Yb, Zb, Xa, Ya, Za, 6);   // ks=5
        STEP(Xa, Ya, Za, Xb, Yb, Zb, 7);   // ks=6
        STEP_LAST(Xb, Yb, Zb);             // ks=7

        // ---- folded -halfE2 chunk: acc += ones * (-h) ----
        const uint32_t hbase = sb + 65536u + (uint32_t)nw * 1024u + (uint32_t)lane * 8u;
#pragma unroll
        for (int pp = 0; pp < 4; pp++) {
            uint2 hp;
            LDS64(hp, hbase + pp * 256u);
            uint2 bh0 = {hp.x, 0u};
            uint2 bh1 = {hp.y, 0u};
            int n0 = pp * 2, n1 = pp * 2 + 1;
            mma_tf32(&acc[(0 * 8 + n0) * 4], aones, bh0);
            mma_tf32(&acc[(1 * 8 + n0) * 4], aones, bh0);
            mma_tf32(&acc[(0 * 8 + n1) * 4], aones, bh1);
            mma_tf32(&acc[(1 * 8 + n1) * 4], aones, bh1);
        }

        // ---- epilogue: pure register argmax ----
#pragma unroll
        for (int ms = 0; ms < 2; ms++)
#pragma unroll
            for (int n = 0; n < 8; n++) {
                int tokb = i * TT + nw * 64 + n * 8 + (lane & 3) * 2;
                const float* d = &acc[(ms * 8 + n) * 4];
#pragma unroll
                for (int j = 0; j < 4; j++) {
                    int tok = tokb + (j & 1);
                    float v = d[j];
                    int s = ms * 2 + (j >> 1);
                    if (v > best[s]) { best[s] = v; bidx[s] = tok; }
                }
            }

        __syncthreads();
        if (i + 2 < NTILES) {
            const char* src = (const char*)&g_B[i + 2][0];
            uint32_t dst = smb + SM_B0 + (uint32_t)(i & 1) * STAGE_BYTES;
#pragma unroll
            for (int it = 0; it < 17; it++) {
                int off = it * NTHREADS * 16 + tid * 16;
                CP_ASYNC16(dst + off, src + off);
            }
            CP_COMMIT();
        }
    }

    // ---- merge across the 4 lanes sharing each row ----
#pragma unroll
    for (int s = 0; s < 4; s++) {
#pragma unroll
        for (int off = 1; off <= 2; off <<= 1) {
            float os = __shfl_xor_sync(0xffffffffu, best[s], off);
            int   oi = __shfl_xor_sync(0xffffffffu, bidx[s], off);
            if (os > best[s] || (os == best[s] && oi < bidx[s])) {
                best[s] = os; bidx[s] = oi;
            }
        }
    }

    float* REDS = (float*)(sm + SM_REDS);
    int*   REDI = (int*)(sm + SM_REDI);
    int*   QIDX = (int*)(sm + SM_QIDX);
    if ((lane & 3) == 0) {
#pragma unroll
        for (int s = 0; s < 4; s++) {
            int row = mw * 32 + (s >> 1) * 16 + (lane >> 2) + (s & 1) * 8;
            REDS[row * 2 + nw] = best[s];
            REDI[row * 2 + nw] = bidx[s];
        }
    }
    __syncthreads();

    if (tid < QB) {
        float s0 = REDS[tid * 2], s1 = REDS[tid * 2 + 1];
        int   i0 = REDI[tid * 2], i1 = REDI[tid * 2 + 1];
        int bi = (s1 > s0 || (s1 == s0 && i1 < i0)) ? i1 : i0;
        QIDX[tid] = bi;
        idxout[(size_t)b * CODES + c0 + tid] = (float)bi;
    }
    __syncthreads();

    // ---- gather x_out ----
#pragma unroll
    for (int it = 0; it < (EMB * QB) / NTHREADS; ++it) {
        int idx = it * NTHREADS + tid;
        int q = idx & (QB - 1);
        int j = idx >> 7;
        xout[(size_t)b * EMB * CODES + (size_t)j * CODES + c0 + q] =
            e[(size_t)QIDX[q] * EMB + j];
    }
}

extern "C" void kernel_launch(void* const* d_in, const int* in_sizes, int n_in,
                              void* d_out, int out_size) {
    const float* x = (const float*)d_in[0];   // [16, 64, 16384]
    const float* e = (const float*)d_in[1];   // [1024, 64]
    int B = in_sizes[0] / (EMB * CODES);

    float* xout   = (float*)d_out;
    float* idxout = xout + (size_t)B * EMB * CODES;

    pre_kernel<<<NTILES, 256>>>(e);

    cudaFuncSetAttribute(vq_kernel, cudaFuncAttributeMaxDynamicSharedMemorySize, SM_TOTAL);
    dim3 grid(CODES / QB, B);
    vq_kernel<<<grid, NTHREADS, SM_TOTAL>>>(x, e, xout, idxout);
}

// round 10
// speedup vs baseline: 1.2242x; 1.0124x over previous
#include <cuda_runtime.h>
#include <cstdint>

#define EMB      64
#define CODES    16384
#define NT       1024
#define QB       128
#define NTHREADS 256
#define NSUB     16          // 16 subtiles of 64 tokens
#define NST      8           // subtiles per group

// per subtile (64 tokens): products [split2][ks8][pair4][lane32][4]f = 8192 floats,
// H frags [pair4][lane32][2]f = 256 floats @8192; pad to 8704 floats (34816 B)
#define SUB_FLOATS 8704
#define SUB_BYTES  (SUB_FLOATS * 4)     // 34816
__device__ float g_B[NSUB][SUB_FLOATS];

__device__ __forceinline__ uint32_t f2tf32(float v) {
    uint32_t r;
    asm("cvt.rna.tf32.f32 %0, %1;" : "=r"(r) : "f"(v));
    return r;
}

__device__ __forceinline__ void mma_tf32(float* d, uint4 a, uint2 b) {
    asm volatile(
        "mma.sync.aligned.m16n8k8.row.col.f32.tf32.tf32.f32 "
        "{%0,%1,%2,%3},{%4,%5,%6,%7},{%8,%9},{%0,%1,%2,%3};"
        : "+f"(d[0]), "+f"(d[1]), "+f"(d[2]), "+f"(d[3])
        : "r"(a.x), "r"(a.y), "r"(a.z), "r"(a.w), "r"(b.x), "r"(b.y));
}

#define CP_ASYNC16(dst, src) \
    asm volatile("cp.async.cg.shared.global [%0], [%1], 16;" :: "r"(dst), "l"(src))
#define CP_COMMIT()  asm volatile("cp.async.commit_group;" ::: "memory")
#define CP_WAIT(n)   asm volatile("cp.async.wait_group %0;" :: "n"(n) : "memory")
#define BARG(id)     asm volatile("bar.sync %0, 128;" :: "r"(id) : "memory")
#define LDS128(v, addr) \
    asm volatile("ld.shared.v4.b32 {%0,%1,%2,%3}, [%4];" \
        : "=r"((v).x), "=r"((v).y), "=r"((v).z), "=r"((v).w) : "r"(addr))
#define LDS64(v, addr) \
    asm volatile("ld.shared.v2.b32 {%0,%1}, [%2];" \
        : "=r"((v).x), "=r"((v).y) : "r"(addr))

__device__ __forceinline__ uint32_t smem_u32(const void* p) {
    uint32_t a;
    asm("{ .reg .u64 t; cvta.to.shared.u64 t, %1; cvt.u32.u64 %0, t; }" : "=r"(a) : "l"(p));
    return a;
}

// ---------------- pre-kernel: tf32 hi/lo splits of E (64-token subtiles) + -h frags ----------------
__global__ void pre_kernel(const float* __restrict__ e) {
    const int sub = blockIdx.x;          // 0..15
    const int tid = threadIdx.x;
    float* base = &g_B[sub][0];

    // product region: ks8 * pair4 * lane32 = 1024 positions, two n-frags each, two splits
    for (int pos = tid; pos < 1024; pos += blockDim.x) {
        int lane = pos & 31;
        int pr   = (pos >> 5) & 3;
        int ks   = pos >> 7;
#pragma unroll
        for (int s = 0; s < 2; s++) {
            int n   = pr * 2 + s;
            int tok = sub * 64 + n * 8 + (lane >> 2);
            int k0  = ks * 8 + (lane & 3);
            float v0 = e[(size_t)tok * EMB + k0];
            float v1 = e[(size_t)tok * EMB + k0 + 4];
            uint32_t h0 = f2tf32(v0), h1 = f2tf32(v1);
            uint32_t L0 = f2tf32(v0 - __uint_as_float(h0));
            uint32_t L1 = f2tf32(v1 - __uint_as_float(h1));
            int off = ks * 512 + pr * 128 + lane * 4 + s * 2;
            base[off]          = __uint_as_float(h0);
            base[off + 1]      = __uint_as_float(h1);
            base[4096 + off]     = __uint_as_float(L0);
            base[4096 + off + 1] = __uint_as_float(L1);
        }
    }

    // H region: [pair4][lane32][2] — B fragment of folded -halfE2 chunk
    for (int idx = tid; idx < 256; idx += blockDim.x) {
        int lane = idx & 31;
        int rest = idx >> 5;     // 0..7
        int pr = rest >> 1;
        int s  = rest & 1;
        int n  = pr * 2 + s;
        int tok = sub * 64 + n * 8 + (lane >> 2);
        int k = lane & 3;
        float val = 0.f;
        if (k < 2) {
            const float* row = e + (size_t)tok * EMB;
            float h = 0.f;
#pragma unroll
            for (int kk = 0; kk < EMB; kk++) h += row[kk] * row[kk];
            float nh = -0.5f * h;
            uint32_t hh = f2tf32(nh);
            if (k == 0) val = __uint_as_float(hh);
            else        val = __uint_as_float(f2tf32(nh - __uint_as_float(hh)));
        }
        base[8192 + (pr * 32 + lane) * 2 + s] = val;
    }
}

// ---------------- SMEM layout (bytes) ----------------
#define SM_A     0                         // 65536: [split2][mw4][ms2][ks8][lane32][4]f
#define SM_ST    65536                     // 4 stage buffers (group*2 + stage) * SUB_BYTES
#define SM_REDS  (SM_ST + 4 * SUB_BYTES)   // 204800: 128*2 floats
#define SM_REDI  (SM_REDS + 1024)
#define SM_QIDX  (SM_REDI + 1024)
#define SM_TOTAL (SM_QIDX + 512)           // 207360

#define LOAD_A(A, ksn) \
    LDS128(A[0], a0base + (ksn) * 512u); \
    LDS128(A[1], a0base + 4096u + (ksn) * 512u); \
    LDS128(A[2], a1base + (ksn) * 512u); \
    LDS128(A[3], a1base + 4096u + (ksn) * 512u)

#define LOAD_B(B0, B1, ksn) \
    LDS128(B0[0], bpair + (ksn) * 2048u); \
    LDS128(B0[1], bpair + (ksn) * 2048u + 512u); \
    LDS128(B0[2], bpair + (ksn) * 2048u + 1024u); \
    LDS128(B0[3], bpair + (ksn) * 2048u + 1536u); \
    LDS128(B1[0], bpair + 16384u + (ksn) * 2048u); \
    LDS128(B1[1], bpair + 16384u + (ksn) * 2048u + 512u); \
    LDS128(B1[2], bpair + 16384u + (ksn) * 2048u + 1024u); \
    LDS128(B1[3], bpair + 16384u + (ksn) * 2048u + 1536u)

#define PASSX(Alo, Ahi, B) do { \
    uint2 _b; \
    _b = make_uint2(B[0].x, B[0].y); mma_tf32(&acc[0],  Alo, _b); mma_tf32(&acc[32], Ahi, _b); \
    _b = make_uint2(B[0].z, B[0].w); mma_tf32(&acc[4],  Alo, _b); mma_tf32(&acc[36], Ahi, _b); \
    _b = make_uint2(B[1].x, B[1].y); mma_tf32(&acc[8],  Alo, _b); mma_tf32(&acc[40], Ahi, _b); \
    _b = make_uint2(B[1].z, B[1].w); mma_tf32(&acc[12], Alo, _b); mma_tf32(&acc[44], Ahi, _b); \
    _b = make_uint2(B[2].x, B[2].y); mma_tf32(&acc[16], Alo, _b); mma_tf32(&acc[48], Ahi, _b); \
    _b = make_uint2(B[2].z, B[2].w); mma_tf32(&acc[20], Alo, _b); mma_tf32(&acc[52], Ahi, _b); \
    _b = make_uint2(B[3].x, B[3].y); mma_tf32(&acc[24], Alo, _b); mma_tf32(&acc[56], Ahi, _b); \
    _b = make_uint2(B[3].z, B[3].w); mma_tf32(&acc[28], Alo, _b); mma_tf32(&acc[60], Ahi, _b); \
} while (0)

#define STEP(A, B0, B1, An, B0n, B1n, KSN) \
    PASSX(A[0], A[1], B0); \
    LOAD_A(An, KSN); \
    PASSX(A[0], A[1], B1); \
    LOAD_B(B0n, B1n, KSN); \
    PASSX(A[2], A[3], B0)

#define STEP_LAST(A, B0, B1) \
    PASSX(A[0], A[1], B0); \
    PASSX(A[0], A[1], B1); \
    PASSX(A[2], A[3], B0)

__global__ __launch_bounds__(NTHREADS, 1) void vq_kernel(
    const float* __restrict__ x,      // [B, EMB, CODES]
    const float* __restrict__ e,      // [NT, EMB]
    float* __restrict__ xout,
    float* __restrict__ idxout)
{
    extern __shared__ uint8_t sm[];
    const uint32_t smb = smem_u32(sm);
    const int tid  = threadIdx.x;
    const int warp = tid >> 5;
    const int lane = tid & 31;
    const int grp  = warp >> 2;       // 0: tokens 0-511, 1: tokens 512-1023
    const int mw   = warp & 3;        // rows mw*32 .. +31
    const int gtid = tid & 127;       // thread index within group
    const int b    = blockIdx.y;
    const int c0   = blockIdx.x * QB;

    const uint32_t st_base = smb + SM_ST + (uint32_t)grp * 2u * SUB_BYTES;

    // ---- cp.async prologue first (overlap with A pack): subtiles grp*8, grp*8+1 ----
#pragma unroll
    for (int st = 0; st < 2; st++) {
        const char* src = (const char*)&g_B[grp * NST + st][0];
        uint32_t dst = st_base + st * SUB_BYTES;
#pragma unroll
        for (int it = 0; it < 17; it++) {
            int off = it * 128 * 16 + gtid * 16;
            CP_ASYNC16(dst + off, src + off);
        }
        CP_COMMIT();
    }

    // ---- pack A fragments: tf32 hi/lo of x[b][k][c0+r], per-lane layout ----
    const float* xb = x + (size_t)b * EMB * CODES + c0;
    for (int p = tid; p < 2048; p += NTHREADS) {
        int ln = p & 31;
        int ks = (p >> 5) & 7;
        int ms = (p >> 8) & 1;
        int w  = p >> 9;
        int r  = w * 32 + ms * 16 + (ln >> 2);
        int k0 = ks * 8 + (ln & 3);
        float v00 = xb[(size_t)k0 * CODES + r];
        float v10 = xb[(size_t)k0 * CODES + r + 8];
        float v01 = xb[(size_t)(k0 + 4) * CODES + r];
        float v11 = xb[(size_t)(k0 + 4) * CODES + r + 8];
        uint32_t h0 = f2tf32(v00), h1 = f2tf32(v10), h2 = f2tf32(v01), h3 = f2tf32(v11);
        uint4 hi = {h0, h1, h2, h3};
        uint4 lo = {f2tf32(v00 - __uint_as_float(h0)),
                    f2tf32(v10 - __uint_as_float(h1)),
                    f2tf32(v01 - __uint_as_float(h2)),
                    f2tf32(v11 - __uint_as_float(h3))};
        int off = w * 8192 + ms * 4096 + ks * 512 + ln * 16;
        *(uint4*)(sm + SM_A + off)         = hi;
        *(uint4*)(sm + SM_A + 32768 + off) = lo;
    }
    __syncthreads();    // A visible to all warps

    float best[4];
    int   bidx[4];
#pragma unroll
    for (int s = 0; s < 4; s++) { best[s] = -3.0e38f; bidx[s] = 0; }

    const uint32_t onec = ((lane & 3) < 2) ? 0x3F800000u : 0u;
    const uint4 aones = {onec, onec, 0u, 0u};

    const uint32_t a0base = smb + SM_A + (uint32_t)mw * 8192u + (uint32_t)lane * 16u;
    const uint32_t a1base = a0base + 32768u;
    const int barid = 1 + grp;

    for (int st = 0; st < NST; st++) {
        if (st < NST - 2) { CP_WAIT(1); } else { CP_WAIT(0); }
        BARG(barid);

        const uint32_t sb = st_base + (uint32_t)(st & 1) * SUB_BYTES;
        const uint32_t bpair = sb + (uint32_t)lane * 16u;
        float acc[64];
#pragma unroll
        for (int z = 0; z < 64; z++) acc[z] = 0.f;

        // ---- ping-pong mainloop, loads threaded between HMMA passes ----
        uint4 Xa[4], Ya[4], Za[4];
        uint4 Xb[4], Yb[4], Zb[4];
        LOAD_A(Xa, 0);
        LOAD_B(Ya, Za, 0);
        STEP(Xa, Ya, Za, Xb, Yb, Zb, 1);
        STEP(Xb, Yb, Zb, Xa, Ya, Za, 2);
        STEP(Xa, Ya, Za, Xb, Yb, Zb, 3);
        STEP(Xb, Yb, Zb, Xa, Ya, Za, 4);
        STEP(Xa, Ya, Za, Xb, Yb, Zb, 5);
        STEP(Xb, Yb, Zb, Xa, Ya, Za, 6);
        STEP(Xa, Ya, Za, Xb, Yb, Zb, 7);
        STEP_LAST(Xb, Yb, Zb);

        // ---- folded -halfE2 chunk ----
        const uint32_t hbase = sb + 32768u + (uint32_t)lane * 8u;
#pragma unroll
        for (int pp = 0; pp < 4; pp++) {
            uint2 hp;
            LDS64(hp, hbase + pp * 256u);
            uint2 bh0 = {hp.x, 0u};
            uint2 bh1 = {hp.y, 0u};
            int n0 = pp * 2, n1 = pp * 2 + 1;
            mma_tf32(&acc[(0 * 8 + n0) * 4], aones, bh0);
            mma_tf32(&acc[(1 * 8 + n0) * 4], aones, bh0);
            mma_tf32(&acc[(0 * 8 + n1) * 4], aones, bh1);
            mma_tf32(&acc[(1 * 8 + n1) * 4], aones, bh1);
        }

        // ---- epilogue: register argmax (tokens ascending within group) ----
        const int tbase = (grp * NST + st) * 64;
#pragma unroll
        for (int ms = 0; ms < 2; ms++)
#pragma unroll
            for (int n = 0; n < 8; n++) {
                int tokb = tbase + n * 8 + (lane & 3) * 2;
                const float* d = &acc[(ms * 8 + n) * 4];
#pragma unroll
                for (int j = 0; j < 4; j++) {
                    int tok = tokb + (j & 1);
                    float v = d[j];
                    int s = ms * 2 + (j >> 1);
                    if (v > best[s]) { best[s] = v; bidx[s] = tok; }
                }
            }

        BARG(barid);   // group done reading stage before refill
        if (st + 2 < NST) {
            const char* src = (const char*)&g_B[grp * NST + st + 2][0];
            uint32_t dst = st_base + (uint32_t)(st & 1) * SUB_BYTES;
#pragma unroll
            for (int it = 0; it < 17; it++) {
                int off = it * 128 * 16 + gtid * 16;
                CP_ASYNC16(dst + off, src + off);
            }
            CP_COMMIT();
        }
    }

    // ---- merge across the 4 lanes sharing each row ----
#pragma unroll
    for (int s = 0; s < 4; s++) {
#pragma unroll
        for (int off = 1; off <= 2; off <<= 1) {
            float os = __shfl_xor_sync(0xffffffffu, best[s], off);
            int   oi = __shfl_xor_sync(0xffffffffu, bidx[s], off);
            if (os > best[s] || (os == best[s] && oi < bidx[s])) {
                best[s] = os; bidx[s] = oi;
            }
        }
    }

    float* REDS = (float*)(sm + SM_REDS);
    int*   REDI = (int*)(sm + SM_REDI);
    int*   QIDX = (int*)(sm + SM_QIDX);
    if ((lane & 3) == 0) {
#pragma unroll
        for (int s = 0; s < 4; s++) {
            int row = mw * 32 + (s >> 1) * 16 + (lane >> 2) + (s & 1) * 8;
            REDS[row * 2 + grp] = best[s];
            REDI[row * 2 + grp] = bidx[s];
        }
    }
    __syncthreads();

    if (tid < QB) {
        float s0 = REDS[tid * 2], s1 = REDS[tid * 2 + 1];
        int   i0 = REDI[tid * 2], i1 = REDI[tid * 2 + 1];
        int bi = (s1 > s0) ? i1 : i0;   // group0 indices always lower; tie -> i0
        QIDX[tid] = bi;
        idxout[(size_t)b * CODES + c0 + tid] = (float)bi;
    }
    __syncthreads();

    // ---- gather x_out ----
#pragma unroll
    for (int it = 0; it < (EMB * QB) / NTHREADS; ++it) {
        int idx = it * NTHREADS + tid;
        int q = idx & (QB - 1);
        int j = idx >> 7;
        xout[(size_t)b * EMB * CODES + (size_t)j * CODES + c0 + q] =
            e[(size_t)QIDX[q] * EMB + j];
    }
}

extern "C" void kernel_launch(void* const* d_in, const int* in_sizes, int n_in,
                              void* d_out, int out_size) {
    const float* x = (const float*)d_in[0];   // [16, 64, 16384]
    const float* e = (const float*)d_in[1];   // [1024, 64]
    int B = in_sizes[0] / (EMB * CODES);

    float* xout   = (float*)d_out;
    float* idxout = xout + (size_t)B * EMB * CODES;

    pre_kernel<<<NSUB, 256>>>(e);

    cudaFuncSetAttribute(vq_kernel, cudaFuncAttributeMaxDynamicSharedMemorySize, SM_TOTAL);
    dim3 grid(CODES / QB, B);
    vq_kernel<<<grid, NTHREADS, SM_TOTAL>>>(x, e, xout, idxout);
}

// round 12
// speedup vs baseline: 1.6629x; 1.3583x over previous
#include <cuda_runtime.h>
#include <cuda_fp16.h>
#include <cstdint>

#define EMB      64
#define CODES    16384
#define NT       1024
#define QB       128
#define NTHREADS 256
#define NSUB     16
#define NST      8

// per 64-token subtile: products [split2][ks4][pair4][lane32][4reg] = 16384 B,
// H frags [pair4][lane32][4reg] = 2048 B  -> 18432 B
#define SUB_BYTES  18432
#define SUB_FLOATS (SUB_BYTES / 4)
__device__ float g_B[NSUB][SUB_FLOATS];

// pack two f32 into f16x2 (lo -> low half, hi -> high half)
#define PACKH(d, lo, hi) \
    asm("cvt.rn.f16x2.f32 %0, %1, %2;" : "=r"(d) : "f"(hi), "f"(lo))

// f32 -> f16 -> f32 round-trip via PTX (no header intrinsics needed)
__device__ __forceinline__ float f16_rt(float v) {
    float r;
    asm("{ .reg .f16 t; cvt.rn.f16.f32 t, %1; cvt.f32.f16 %0, t; }" : "=f"(r) : "f"(v));
    return r;
}
__device__ __forceinline__ float lo_res(float v) { return v - f16_rt(v); }

__device__ __forceinline__ void mma_f16(float* d, uint4 a, uint2 b) {
    asm volatile(
        "mma.sync.aligned.m16n8k16.row.col.f32.f16.f16.f32 "
        "{%0,%1,%2,%3},{%4,%5,%6,%7},{%8,%9},{%0,%1,%2,%3};"
        : "+f"(d[0]), "+f"(d[1]), "+f"(d[2]), "+f"(d[3])
        : "r"(a.x), "r"(a.y), "r"(a.z), "r"(a.w), "r"(b.x), "r"(b.y));
}

#define CP_ASYNC16(dst, src) \
    asm volatile("cp.async.cg.shared.global [%0], [%1], 16;" :: "r"(dst), "l"(src))
#define CP_COMMIT()  asm volatile("cp.async.commit_group;" ::: "memory")
#define CP_WAIT(n)   asm volatile("cp.async.wait_group %0;" :: "n"(n) : "memory")
#define BARG(id)     asm volatile("bar.sync %0, 128;" :: "r"(id) : "memory")
#define LDS128(v, addr) \
    asm volatile("ld.shared.v4.b32 {%0,%1,%2,%3}, [%4];" \
        : "=r"((v).x), "=r"((v).y), "=r"((v).z), "=r"((v).w) : "r"(addr))

__device__ __forceinline__ uint32_t smem_u32(const void* p) {
    uint32_t a;
    asm("{ .reg .u64 t; cvta.to.shared.u64 t, %1; cvt.u32.u64 %0, t; }" : "=r"(a) : "l"(p));
    return a;
}

// ---------------- pre-kernel: fp16 hi/lo splits of E + -halfE2 fold fragments ----------------
__global__ void pre_kernel(const float* __restrict__ e) {
    const int sub = blockIdx.x;
    const int tid = threadIdx.x;
    char* base = (char*)&g_B[sub][0];

    // product region: ks4 * pair4 * lane32 = 512 positions; uint4 = {b0,b1} of 2 n-frags
    for (int pos = tid; pos < 512; pos += blockDim.x) {
        int lane = pos & 31;
        int pr   = (pos >> 5) & 3;
        int ks   = pos >> 7;
        int c = lane & 3, n = lane >> 2;
        int k0 = ks * 16 + 2 * c;
        uint32_t hi[4], lo[4];
#pragma unroll
        for (int half = 0; half < 2; half++) {
            int tok = sub * 64 + (pr * 2 + half) * 8 + n;
            const float* row = e + (size_t)tok * EMB;
            float v0 = row[k0], v1 = row[k0 + 1], v2 = row[k0 + 8], v3 = row[k0 + 9];
            PACKH(hi[half * 2 + 0], v0, v1);
            PACKH(hi[half * 2 + 1], v2, v3);
            PACKH(lo[half * 2 + 0], lo_res(v0), lo_res(v1));
            PACKH(lo[half * 2 + 1], lo_res(v2), lo_res(v3));
        }
        int off = ks * 2048 + pr * 512 + lane * 16;
        *(uint4*)(base + off)        = make_uint4(hi[0], hi[1], hi[2], hi[3]);
        *(uint4*)(base + 8192 + off) = make_uint4(lo[0], lo[1], lo[2], lo[3]);
    }

    // H region: 3-term fp16 split of -0.5*||e||^2 at k=0,1,2
    for (int pos = tid; pos < 128; pos += blockDim.x) {
        int lane = pos & 31;
        int pr   = pos >> 5;
        int c = lane & 3, n = lane >> 2;
        uint32_t regs[4] = {0u, 0u, 0u, 0u};
#pragma unroll
        for (int half = 0; half < 2; half++) {
            int tok = sub * 64 + (pr * 2 + half) * 8 + n;
            const float* row = e + (size_t)tok * EMB;
            float h = 0.f;
#pragma unroll
            for (int kk = 0; kk < EMB; kk++) h += row[kk] * row[kk];
            float nh = -0.5f * h;
            float r1 = nh - f16_rt(nh);
            float r2 = r1 - f16_rt(r1);
            uint32_t b0 = 0u;
            if (c == 0)      PACKH(b0, nh, r1);     // k=0: h0, k=1: h1
            else if (c == 1) PACKH(b0, r2, 0.f);    // k=2: h2, k=3: 0
            regs[half * 2] = b0;                    // b1 (k>=8) stays 0
        }
        *(uint4*)(base + 16384 + pr * 512 + lane * 16) =
            make_uint4(regs[0], regs[1], regs[2], regs[3]);
    }
}

// ---------------- SMEM layout (bytes) ----------------
#define SM_A     0                          // 32768: [split2][mw4][ms2][ks4][lane32][4reg]
#define SM_ST    32768                      // 4 stage buffers
#define SM_REDS  (SM_ST + 4 * SUB_BYTES)    // 106496
#define SM_REDI  (SM_REDS + 1024)
#define SM_QIDX  (SM_REDI + 1024)
#define SM_TOTAL (SM_QIDX + 512)            // 109056

#define LOAD_A(A, ksn) \
    LDS128(A[0], a0base + (ksn) * 512u); \
    LDS128(A[1], a0base + 2048u + (ksn) * 512u); \
    LDS128(A[2], a1base + (ksn) * 512u); \
    LDS128(A[3], a1base + 2048u + (ksn) * 512u)

#define LOAD_B0(B0, ksn) \
    LDS128(B0[0], bpair + (ksn) * 2048u); \
    LDS128(B0[1], bpair + (ksn) * 2048u + 512u); \
    LDS128(B0[2], bpair + (ksn) * 2048u + 1024u); \
    LDS128(B0[3], bpair + (ksn) * 2048u + 1536u)

#define LOAD_B1(B1, ksn) \
    LDS128(B1[0], bpair + 8192u + (ksn) * 2048u); \
    LDS128(B1[1], bpair + 8192u + (ksn) * 2048u + 512u); \
    LDS128(B1[2], bpair + 8192u + (ksn) * 2048u + 1024u); \
    LDS128(B1[3], bpair + 8192u + (ksn) * 2048u + 1536u)

#define PASSX(Am0, Am1, B) do { \
    uint2 _b; \
    _b = make_uint2(B[0].x, B[0].y); mma_f16(&acc[0],  Am0, _b); mma_f16(&acc[32], Am1, _b); \
    _b = make_uint2(B[0].z, B[0].w); mma_f16(&acc[4],  Am0, _b); mma_f16(&acc[36], Am1, _b); \
    _b = make_uint2(B[1].x, B[1].y); mma_f16(&acc[8],  Am0, _b); mma_f16(&acc[40], Am1, _b); \
    _b = make_uint2(B[1].z, B[1].w); mma_f16(&acc[12], Am0, _b); mma_f16(&acc[44], Am1, _b); \
    _b = make_uint2(B[2].x, B[2].y); mma_f16(&acc[16], Am0, _b); mma_f16(&acc[48], Am1, _b); \
    _b = make_uint2(B[2].z, B[2].w); mma_f16(&acc[20], Am0, _b); mma_f16(&acc[52], Am1, _b); \
    _b = make_uint2(B[3].x, B[3].y); mma_f16(&acc[24], Am0, _b); mma_f16(&acc[56], Am1, _b); \
    _b = make_uint2(B[3].z, B[3].w); mma_f16(&acc[28], Am0, _b); mma_f16(&acc[60], Am1, _b); \
} while (0)

// 4 products: X0E0, X0E1, X1E0, X1E1 — loads for ks=KSN threaded between passes
#define STEP(A, B0, B1, An, B0n, B1n, KSN) \
    PASSX(A[0], A[1], B0); \
    LOAD_A(An, KSN); \
    PASSX(A[0], A[1], B1); \
    LOAD_B0(B0n, KSN); \
    PASSX(A[2], A[3], B0); \
    LOAD_B1(B1n, KSN); \
    PASSX(A[2], A[3], B1)

#define STEP_LAST(A, B0, B1) \
    PASSX(A[0], A[1], B0); \
    PASSX(A[0], A[1], B1); \
    PASSX(A[2], A[3], B0); \
    PASSX(A[2], A[3], B1)

__global__ __launch_bounds__(NTHREADS, 1) void vq_kernel(
    const float* __restrict__ x,      // [B, EMB, CODES]
    const float* __restrict__ e,      // [NT, EMB]
    float* __restrict__ xout,
    float* __restrict__ idxout)
{
    extern __shared__ uint8_t sm[];
    const uint32_t smb = smem_u32(sm);
    const int tid  = threadIdx.x;
    const int warp = tid >> 5;
    const int lane = tid & 31;
    const int grp  = warp >> 2;
    const int mw   = warp & 3;
    const int gtid = tid & 127;
    const int b    = blockIdx.y;
    const int c0   = blockIdx.x * QB;

    const uint32_t st_base = smb + SM_ST + (uint32_t)grp * 2u * SUB_BYTES;

    // ---- cp.async prologue: subtiles grp*8, grp*8+1 ----
#pragma unroll
    for (int st = 0; st < 2; st++) {
        const char* src = (const char*)&g_B[grp * NST + st][0];
        uint32_t dst = st_base + st * SUB_BYTES;
#pragma unroll
        for (int it = 0; it < 9; it++) {
            int off = it * 128 * 16 + gtid * 16;
            CP_ASYNC16(dst + off, src + off);
        }
        CP_COMMIT();
    }

    // ---- pack A fragments: fp16 hi/lo of x[b][k][c0+r], m16n8k16 A layout ----
    const float* xb = x + (size_t)b * EMB * CODES + c0;
    for (int p = tid; p < 1024; p += NTHREADS) {
        int ln = p & 31;
        int ks = (p >> 5) & 3;
        int ms = (p >> 7) & 1;
        int w  = p >> 8;
        int r  = w * 32 + ms * 16 + (ln >> 2);
        int c  = ln & 3;
        int k0 = ks * 16 + 2 * c;
        float v00 = xb[(size_t)k0 * CODES + r];
        float v01 = xb[(size_t)(k0 + 1) * CODES + r];
        float v02 = xb[(size_t)(k0 + 8) * CODES + r];
        float v03 = xb[(size_t)(k0 + 9) * CODES + r];
        float v10 = xb[(size_t)k0 * CODES + r + 8];
        float v11 = xb[(size_t)(k0 + 1) * CODES + r + 8];
        float v12 = xb[(size_t)(k0 + 8) * CODES + r + 8];
        float v13 = xb[(size_t)(k0 + 9) * CODES + r + 8];
        uint32_t a0, a1, a2, a3, l0, l1, l2, l3;
        PACKH(a0, v00, v01); PACKH(a1, v10, v11);
        PACKH(a2, v02, v03); PACKH(a3, v12, v13);
        PACKH(l0, lo_res(v00), lo_res(v01)); PACKH(l1, lo_res(v10), lo_res(v11));
        PACKH(l2, lo_res(v02), lo_res(v03)); PACKH(l3, lo_res(v12), lo_res(v13));
        int off = w * 4096 + ms * 2048 + ks * 512 + ln * 16;
        *(uint4*)(sm + SM_A + off)          = make_uint4(a0, a1, a2, a3);
        *(uint4*)(sm + SM_A + 16384 + off)  = make_uint4(l0, l1, l2, l3);
    }
    __syncthreads();

    float best[4];
    int   bidx[4];
#pragma unroll
    for (int s = 0; s < 4; s++) { best[s] = -3.0e38f; bidx[s] = 0; }

    // A "ones at k=0,1,2" fragment for the -h fold
    const int cc = lane & 3;
    const uint32_t onep = (cc == 0) ? 0x3C003C00u : (cc == 1 ? 0x00003C00u : 0u);
    const uint4 aones = {onep, onep, 0u, 0u};

    const uint32_t a0base = smb + SM_A + (uint32_t)mw * 4096u + (uint32_t)lane * 16u;
    const uint32_t a1base = a0base + 16384u;
    const int barid = 1 + grp;

    for (int st = 0; st < NST; st++) {
        if (st < NST - 2) { CP_WAIT(1); } else { CP_WAIT(0); }
        BARG(barid);

        const uint32_t sb = st_base + (uint32_t)(st & 1) * SUB_BYTES;
        const uint32_t bpair = sb + (uint32_t)lane * 16u;
        float acc[64];
#pragma unroll
        for (int z = 0; z < 64; z++) acc[z] = 0.f;

        uint4 Xa[4], Ya[4], Za[4];
        uint4 Xb[4], Yb[4], Zb[4];
        LOAD_A(Xa, 0);
        LOAD_B0(Ya, 0);
        LOAD_B1(Za, 0);
        STEP(Xa, Ya, Za, Xb, Yb, Zb, 1);
        STEP(Xb, Yb, Zb, Xa, Ya, Za, 2);
        STEP(Xa, Ya, Za, Xb, Yb, Zb, 3);
        STEP_LAST(Xb, Yb, Zb);

        // ---- folded -halfE2 chunk ----
        const uint32_t hbase = sb + 16384u + (uint32_t)lane * 16u;
#pragma unroll
        for (int pp = 0; pp < 4; pp++) {
            uint4 H;
            LDS128(H, hbase + pp * 512u);
            uint2 bA = make_uint2(H.x, H.y);
            uint2 bB = make_uint2(H.z, H.w);
            int n0 = pp * 2, n1 = pp * 2 + 1;
            mma_f16(&acc[n0 * 4],      aones, bA);
            mma_f16(&acc[32 + n0 * 4], aones, bA);
            mma_f16(&acc[n1 * 4],      aones, bB);
            mma_f16(&acc[32 + n1 * 4], aones, bB);
        }

        // ---- epilogue: register argmax ----
        const int tbase = (grp * NST + st) * 64;
#pragma unroll
        for (int ms = 0; ms < 2; ms++)
#pragma unroll
            for (int n = 0; n < 8; n++) {
                int tokb = tbase + n * 8 + (lane & 3) * 2;
                const float* d = &acc[(ms * 8 + n) * 4];
#pragma unroll
                for (int j = 0; j < 4; j++) {
                    int tok = tokb + (j & 1);
                    float v = d[j];
                    int s = ms * 2 + (j >> 1);
                    if (v > best[s]) { best[s] = v; bidx[s] = tok; }
                }
            }

        BARG(barid);
        if (st + 2 < NST) {
            const char* src = (const char*)&g_B[grp * NST + st + 2][0];
            uint32_t dst = st_base + (uint32_t)(st & 1) * SUB_BYTES;
#pragma unroll
            for (int it = 0; it < 9; it++) {
                int off = it * 128 * 16 + gtid * 16;
                CP_ASYNC16(dst + off, src + off);
            }
            CP_COMMIT();
        }
    }

    // ---- merge across the 4 lanes sharing each row ----
#pragma unroll
    for (int s = 0; s < 4; s++) {
#pragma unroll
        for (int off = 1; off <= 2; off <<= 1) {
            float os = __shfl_xor_sync(0xffffffffu, best[s], off);
            int   oi = __shfl_xor_sync(0xffffffffu, bidx[s], off);
            if (os > best[s] || (os == best[s] && oi < bidx[s])) {
                best[s] = os; bidx[s] = oi;
            }
        }
    }

    float* REDS = (float*)(sm + SM_REDS);
    int*   REDI = (int*)(sm + SM_REDI);
    int*   QIDX = (int*)(sm + SM_QIDX);
    if ((lane & 3) == 0) {
#pragma unroll
        for (int s = 0; s < 4; s++) {
            int row = mw * 32 + (s >> 1) * 16 + (lane >> 2) + (s & 1) * 8;
            REDS[row * 2 + grp] = best[s];
            REDI[row * 2 + grp] = bidx[s];
        }
    }
    __syncthreads();

    if (tid < QB) {
        float s0 = REDS[tid * 2], s1 = REDS[tid * 2 + 1];
        int   i0 = REDI[tid * 2], i1 = REDI[tid * 2 + 1];
        int bi = (s1 > s0) ? i1 : i0;   // group0 indices lower; tie -> i0
        QIDX[tid] = bi;
        idxout[(size_t)b * CODES + c0 + tid] = (float)bi;
    }
    __syncthreads();

    // ---- gather x_out ----
#pragma unroll
    for (int it = 0; it < (EMB * QB) / NTHREADS; ++it) {
        int idx = it * NTHREADS + tid;
        int q = idx & (QB - 1);
        int j = idx >> 7;
        xout[(size_t)b * EMB * CODES + (size_t)j * CODES + c0 + q] =
            e[(size_t)QIDX[q] * EMB + j];
    }
}

extern "C" void kernel_launch(void* const* d_in, const int* in_sizes, int n_in,
                              void* d_out, int out_size) {
    const float* x = (const float*)d_in[0];   // [16, 64, 16384]
    const float* e = (const float*)d_in[1];   // [1024, 64]
    int B = in_sizes[0] / (EMB * CODES);

    float* xout   = (float*)d_out;
    float* idxout = xout + (size_t)B * EMB * CODES;

    pre_kernel<<<NSUB, 256>>>(e);

    cudaFuncSetAttribute(vq_kernel, cudaFuncAttributeMaxDynamicSharedMemorySize, SM_TOTAL);
    dim3 grid(CODES / QB, B);
    vq_kernel<<<grid, NTHREADS, SM_TOTAL>>>(x, e, xout, idxout);
}

// round 13
// speedup vs baseline: 1.8781x; 1.1294x over previous
#include <cuda_runtime.h>
#include <cuda_fp16.h>
#include <cstdint>

#define EMB      64
#define CODES    16384
#define NT       1024
#define QB       128
#define NTHREADS 256
#define NSUB     16
#define NST      8

// per 64-token subtile: products [split2][ks4][pair4][lane32][4reg] = 16384 B,
// H frags [pair4][lane32][4reg] = 2048 B  -> 18432 B
#define SUB_BYTES  18432
#define SUB_FLOATS (SUB_BYTES / 4)
__device__ float g_B[NSUB][SUB_FLOATS];

// pack two f32 into f16x2 (lo -> low half, hi -> high half)
#define PACKH(d, lo, hi) \
    asm("cvt.rn.f16x2.f32 %0, %1, %2;" : "=r"(d) : "f"(hi), "f"(lo))

// f32 -> f16 -> f32 round-trip via PTX
__device__ __forceinline__ float f16_rt(float v) {
    float r;
    asm("{ .reg .f16 t; cvt.rn.f16.f32 t, %1; cvt.f32.f16 %0, t; }" : "=f"(r) : "f"(v));
    return r;
}
__device__ __forceinline__ float lo_res(float v) { return v - f16_rt(v); }

__device__ __forceinline__ void mma_f16(float* d, uint4 a, uint2 b) {
    asm volatile(
        "mma.sync.aligned.m16n8k16.row.col.f32.f16.f16.f32 "
        "{%0,%1,%2,%3},{%4,%5,%6,%7},{%8,%9},{%0,%1,%2,%3};"
        : "+f"(d[0]), "+f"(d[1]), "+f"(d[2]), "+f"(d[3])
        : "r"(a.x), "r"(a.y), "r"(a.z), "r"(a.w), "r"(b.x), "r"(b.y));
}

#define CP_ASYNC16(dst, src) \
    asm volatile("cp.async.cg.shared.global [%0], [%1], 16;" :: "r"(dst), "l"(src))
#define CP_COMMIT()  asm volatile("cp.async.commit_group;" ::: "memory")
#define CP_WAIT(n)   asm volatile("cp.async.wait_group %0;" :: "n"(n) : "memory")
#define BARG(id)     asm volatile("bar.sync %0, 128;" :: "r"(id) : "memory")
#define LDS128(v, addr) \
    asm volatile("ld.shared.v4.b32 {%0,%1,%2,%3}, [%4];" \
        : "=r"((v).x), "=r"((v).y), "=r"((v).z), "=r"((v).w) : "r"(addr))

__device__ __forceinline__ uint32_t smem_u32(const void* p) {
    uint32_t a;
    asm("{ .reg .u64 t; cvta.to.shared.u64 t, %1; cvt.u32.u64 %0, t; }" : "=r"(a) : "l"(p));
    return a;
}

// ---------------- pre-kernel: fp16 hi/lo splits of E + -halfE2 fold fragments ----------------
__global__ void pre_kernel(const float* __restrict__ e) {
    const int sub = blockIdx.x;
    const int tid = threadIdx.x;
    char* base = (char*)&g_B[sub][0];

    for (int pos = tid; pos < 512; pos += blockDim.x) {
        int lane = pos & 31;
        int pr   = (pos >> 5) & 3;
        int ks   = pos >> 7;
        int c = lane & 3, n = lane >> 2;
        int k0 = ks * 16 + 2 * c;
        uint32_t hi[4], lo[4];
#pragma unroll
        for (int half = 0; half < 2; half++) {
            int tok = sub * 64 + (pr * 2 + half) * 8 + n;
            const float* row = e + (size_t)tok * EMB;
            float v0 = row[k0], v1 = row[k0 + 1], v2 = row[k0 + 8], v3 = row[k0 + 9];
            PACKH(hi[half * 2 + 0], v0, v1);
            PACKH(hi[half * 2 + 1], v2, v3);
            PACKH(lo[half * 2 + 0], lo_res(v0), lo_res(v1));
            PACKH(lo[half * 2 + 1], lo_res(v2), lo_res(v3));
        }
        int off = ks * 2048 + pr * 512 + lane * 16;
        *(uint4*)(base + off)        = make_uint4(hi[0], hi[1], hi[2], hi[3]);
        *(uint4*)(base + 8192 + off) = make_uint4(lo[0], lo[1], lo[2], lo[3]);
    }

    // H region: 3-term fp16 split of -0.5*||e||^2 at k=0,1,2
    for (int pos = tid; pos < 128; pos += blockDim.x) {
        int lane = pos & 31;
        int pr   = pos >> 5;
        int c = lane & 3, n = lane >> 2;
        uint32_t regs[4] = {0u, 0u, 0u, 0u};
#pragma unroll
        for (int half = 0; half < 2; half++) {
            int tok = sub * 64 + (pr * 2 + half) * 8 + n;
            const float* row = e + (size_t)tok * EMB;
            float h = 0.f;
#pragma unroll
            for (int kk = 0; kk < EMB; kk++) h += row[kk] * row[kk];
            float nh = -0.5f * h;
            float r1 = nh - f16_rt(nh);
            float r2 = r1 - f16_rt(r1);
            uint32_t b0 = 0u;
            if (c == 0)      PACKH(b0, nh, r1);     // k=0: h0, k=1: h1
            else if (c == 1) PACKH(b0, r2, 0.f);    // k=2: h2, k=3: 0
            regs[half * 2] = b0;
        }
        *(uint4*)(base + 16384 + pr * 512 + lane * 16) =
            make_uint4(regs[0], regs[1], regs[2], regs[3]);
    }
}

// ---------------- SMEM layout (bytes) ----------------
#define SM_A     0                          // 32768
#define SM_ST    32768                      // 4 stage buffers
#define SM_REDS  (SM_ST + 4 * SUB_BYTES)    // 106496
#define SM_REDI  (SM_REDS + 1024)
#define SM_QIDX  (SM_REDI + 1024)
#define SM_TOTAL (SM_QIDX + 512)            // 109056

#define LOAD_A(A, ksn) \
    LDS128(A[0], a0base + (ksn) * 512u); \
    LDS128(A[1], a0base + 2048u + (ksn) * 512u); \
    LDS128(A[2], a1base + (ksn) * 512u); \
    LDS128(A[3], a1base + 2048u + (ksn) * 512u)

#define LOAD_B0(B0, ksn) \
    LDS128(B0[0], bpair + (ksn) * 2048u); \
    LDS128(B0[1], bpair + (ksn) * 2048u + 512u); \
    LDS128(B0[2], bpair + (ksn) * 2048u + 1024u); \
    LDS128(B0[3], bpair + (ksn) * 2048u + 1536u)

#define LOAD_B1(B1, ksn) \
    LDS128(B1[0], bpair + 8192u + (ksn) * 2048u); \
    LDS128(B1[1], bpair + 8192u + (ksn) * 2048u + 512u); \
    LDS128(B1[2], bpair + 8192u + (ksn) * 2048u + 1024u); \
    LDS128(B1[3], bpair + 8192u + (ksn) * 2048u + 1536u)

#define PASSX(Am0, Am1, B) do { \
    uint2 _b; \
    _b = make_uint2(B[0].x, B[0].y); mma_f16(&acc[0],  Am0, _b); mma_f16(&acc[32], Am1, _b); \
    _b = make_uint2(B[0].z, B[0].w); mma_f16(&acc[4],  Am0, _b); mma_f16(&acc[36], Am1, _b); \
    _b = make_uint2(B[1].x, B[1].y); mma_f16(&acc[8],  Am0, _b); mma_f16(&acc[40], Am1, _b); \
    _b = make_uint2(B[1].z, B[1].w); mma_f16(&acc[12], Am0, _b); mma_f16(&acc[44], Am1, _b); \
    _b = make_uint2(B[2].x, B[2].y); mma_f16(&acc[16], Am0, _b); mma_f16(&acc[48], Am1, _b); \
    _b = make_uint2(B[2].z, B[2].w); mma_f16(&acc[20], Am0, _b); mma_f16(&acc[52], Am1, _b); \
    _b = make_uint2(B[3].x, B[3].y); mma_f16(&acc[24], Am0, _b); mma_f16(&acc[56], Am1, _b); \
    _b = make_uint2(B[3].z, B[3].w); mma_f16(&acc[28], Am0, _b); mma_f16(&acc[60], Am1, _b); \
} while (0)

// 3 products: X0E0, X0E1, X1E0 (X1E1 residual*residual dropped, ~2^-22 class)
#define STEP(A, B0, B1, An, B0n, B1n, KSN) \
    PASSX(A[0], A[1], B0); \
    LOAD_A(An, KSN); \
    PASSX(A[0], A[1], B1); \
    LOAD_B0(B0n, KSN); \
    PASSX(A[2], A[3], B0); \
    LOAD_B1(B1n, KSN)

#define STEP_LAST(A, B0, B1) \
    PASSX(A[0], A[1], B0); \
    PASSX(A[0], A[1], B1); \
    PASSX(A[2], A[3], B0)

__global__ __launch_bounds__(NTHREADS, 1) void vq_kernel(
    const float* __restrict__ x,      // [B, EMB, CODES]
    const float* __restrict__ e,      // [NT, EMB]
    float* __restrict__ xout,
    float* __restrict__ idxout)
{
    extern __shared__ uint8_t sm[];
    const uint32_t smb = smem_u32(sm);
    const int tid  = threadIdx.x;
    const int warp = tid >> 5;
    const int lane = tid & 31;
    const int grp  = warp >> 2;
    const int mw   = warp & 3;
    const int gtid = tid & 127;
    const int b    = blockIdx.y;
    const int c0   = blockIdx.x * QB;

    const uint32_t st_base = smb + SM_ST + (uint32_t)grp * 2u * SUB_BYTES;

    // ---- cp.async prologue: subtiles grp*8, grp*8+1 ----
#pragma unroll
    for (int st = 0; st < 2; st++) {
        const char* src = (const char*)&g_B[grp * NST + st][0];
        uint32_t dst = st_base + st * SUB_BYTES;
#pragma unroll
        for (int it = 0; it < 9; it++) {
            int off = it * 128 * 16 + gtid * 16;
            CP_ASYNC16(dst + off, src + off);
        }
        CP_COMMIT();
    }

    // ---- pack A fragments: fp16 hi/lo of x[b][k][c0+r], m16n8k16 A layout ----
    const float* xb = x + (size_t)b * EMB * CODES + c0;
    for (int p = tid; p < 1024; p += NTHREADS) {
        int ln = p & 31;
        int ks = (p >> 5) & 3;
        int ms = (p >> 7) & 1;
        int w  = p >> 8;
        int r  = w * 32 + ms * 16 + (ln >> 2);
        int c  = ln & 3;
        int k0 = ks * 16 + 2 * c;
        float v00 = xb[(size_t)k0 * CODES + r];
        float v01 = xb[(size_t)(k0 + 1) * CODES + r];
        float v02 = xb[(size_t)(k0 + 8) * CODES + r];
        float v03 = xb[(size_t)(k0 + 9) * CODES + r];
        float v10 = xb[(size_t)k0 * CODES + r + 8];
        float v11 = xb[(size_t)(k0 + 1) * CODES + r + 8];
        float v12 = xb[(size_t)(k0 + 8) * CODES + r + 8];
        float v13 = xb[(size_t)(k0 + 9) * CODES + r + 8];
        uint32_t a0, a1, a2, a3, l0, l1, l2, l3;
        PACKH(a0, v00, v01); PACKH(a1, v10, v11);
        PACKH(a2, v02, v03); PACKH(a3, v12, v13);
        PACKH(l0, lo_res(v00), lo_res(v01)); PACKH(l1, lo_res(v10), lo_res(v11));
        PACKH(l2, lo_res(v02), lo_res(v03)); PACKH(l3, lo_res(v12), lo_res(v13));
        int off = w * 4096 + ms * 2048 + ks * 512 + ln * 16;
        *(uint4*)(sm + SM_A + off)          = make_uint4(a0, a1, a2, a3);
        *(uint4*)(sm + SM_A + 16384 + off)  = make_uint4(l0, l1, l2, l3);
    }
    __syncthreads();

    float best[4];
    int   bidx[4];
#pragma unroll
    for (int s = 0; s < 4; s++) { best[s] = -3.0e38f; bidx[s] = 0; }

    const int cc = lane & 3;
    const uint32_t onep = (cc == 0) ? 0x3C003C00u : (cc == 1 ? 0x00003C00u : 0u);
    const uint4 aones = {onep, onep, 0u, 0u};

    const uint32_t a0base = smb + SM_A + (uint32_t)mw * 4096u + (uint32_t)lane * 16u;
    const uint32_t a1base = a0base + 16384u;
    const int barid = 1 + grp;

    for (int st = 0; st < NST; st++) {
        if (st < NST - 2) { CP_WAIT(1); } else { CP_WAIT(0); }
        BARG(barid);

        const uint32_t sb = st_base + (uint32_t)(st & 1) * SUB_BYTES;
        const uint32_t bpair = sb + (uint32_t)lane * 16u;
        float acc[64];
#pragma unroll
        for (int z = 0; z < 64; z++) acc[z] = 0.f;

        uint4 Xa[4], Ya[4], Za[4];
        uint4 Xb[4], Yb[4], Zb[4];
        LOAD_A(Xa, 0);
        LOAD_B0(Ya, 0);
        LOAD_B1(Za, 0);
        STEP(Xa, Ya, Za, Xb, Yb, Zb, 1);
        STEP(Xb, Yb, Zb, Xa, Ya, Za, 2);
        STEP(Xa, Ya, Za, Xb, Yb, Zb, 3);
        STEP_LAST(Xb, Yb, Zb);

        // ---- folded -halfE2 chunk ----
        const uint32_t hbase = sb + 16384u + (uint32_t)lane * 16u;
#pragma unroll
        for (int pp = 0; pp < 4; pp++) {
            uint4 H;
            LDS128(H, hbase + pp * 512u);
            uint2 bA = make_uint2(H.x, H.y);
            uint2 bB = make_uint2(H.z, H.w);
            int n0 = pp * 2, n1 = pp * 2 + 1;
            mma_f16(&acc[n0 * 4],      aones, bA);
            mma_f16(&acc[32 + n0 * 4], aones, bA);
            mma_f16(&acc[n1 * 4],      aones, bB);
            mma_f16(&acc[32 + n1 * 4], aones, bB);
        }

        // ---- epilogue: register argmax ----
        const int tbase = (grp * NST + st) * 64;
#pragma unroll
        for (int ms = 0; ms < 2; ms++)
#pragma unroll
            for (int n = 0; n < 8; n++) {
                int tokb = tbase + n * 8 + (lane & 3) * 2;
                const float* d = &acc[(ms * 8 + n) * 4];
#pragma unroll
                for (int j = 0; j < 4; j++) {
                    int tok = tokb + (j & 1);
                    float v = d[j];
                    int s = ms * 2 + (j >> 1);
                    if (v > best[s]) { best[s] = v; bidx[s] = tok; }
                }
            }

        BARG(barid);
        if (st + 2 < NST) {
            const char* src = (const char*)&g_B[grp * NST + st + 2][0];
            uint32_t dst = st_base + (uint32_t)(st & 1) * SUB_BYTES;
#pragma unroll
            for (int it = 0; it < 9; it++) {
                int off = it * 128 * 16 + gtid * 16;
                CP_ASYNC16(dst + off, src + off);
            }
            CP_COMMIT();
        }
    }

    // ---- merge across the 4 lanes sharing each row ----
#pragma unroll
    for (int s = 0; s < 4; s++) {
#pragma unroll
        for (int off = 1; off <= 2; off <<= 1) {
            float os = __shfl_xor_sync(0xffffffffu, best[s], off);
            int   oi = __shfl_xor_sync(0xffffffffu, bidx[s], off);
            if (os > best[s] || (os == best[s] && oi < bidx[s])) {
                best[s] = os; bidx[s] = oi;
            }
        }
    }

    float* REDS = (float*)(sm + SM_REDS);
    int*   REDI = (int*)(sm + SM_REDI);
    int*   QIDX = (int*)(sm + SM_QIDX);
    if ((lane & 3) == 0) {
#pragma unroll
        for (int s = 0; s < 4; s++) {
            int row = mw * 32 + (s >> 1) * 16 + (lane >> 2) + (s & 1) * 8;
            REDS[row * 2 + grp] = best[s];
            REDI[row * 2 + grp] = bidx[s];
        }
    }
    __syncthreads();

    if (tid < QB) {
        float s0 = REDS[tid * 2], s1 = REDS[tid * 2 + 1];
        int   i0 = REDI[tid * 2], i1 = REDI[tid * 2 + 1];
        int bi = (s1 > s0) ? i1 : i0;
        QIDX[tid] = bi;
        idxout[(size_t)b * CODES + c0 + tid] = (float)bi;
    }
    __syncthreads();

    // ---- gather x_out ----
#pragma unroll
    for (int it = 0; it < (EMB * QB) / NTHREADS; ++it) {
        int idx = it * NTHREADS + tid;
        int q = idx & (QB - 1);
        int j = idx >> 7;
        xout[(size_t)b * EMB * CODES + (size_t)j * CODES + c0 + q] =
            e[(size_t)QIDX[q] * EMB + j];
    }
}

extern "C" void kernel_launch(void* const* d_in, const int* in_sizes, int n_in,
                              void* d_out, int out_size) {
    const float* x = (const float*)d_in[0];   // [16, 64, 16384]
    const float* e = (const float*)d_in[1];   // [1024, 64]
    int B = in_sizes[0] / (EMB * CODES);

    float* xout   = (float*)d_out;
    float* idxout = xout + (size_t)B * EMB * CODES;

    pre_kernel<<<NSUB, 256>>>(e);

    cudaFuncSetAttribute(vq_kernel, cudaFuncAttributeMaxDynamicSharedMemorySize, SM_TOTAL);
    dim3 grid(CODES / QB, B);
    vq_kernel<<<grid, NTHREADS, SM_TOTAL>>>(x, e, xout, idxout);
}

// round 14
// speedup vs baseline: 2.3469x; 1.2496x over previous
#include <cuda_runtime.h>
#include <cuda_fp16.h>
#include <cstdint>

#define EMB      64
#define CODES    16384
#define NT       1024
#define QB       128
#define NTHREADS 256
#define NSUB     32          // 32 subtiles of 32 tokens
#define NSTG     16          // subtiles per group

// per 32-token subtile: [split2][ks4][pair2][lane32][uint4] = 8192 B
#define SUB_BYTES  8192
#define SUB_FLOATS (SUB_BYTES / 4)
__device__ float g_B[NSUB][SUB_FLOATS];
__device__ float g_hE2[NT];

#define PACKH(d, lo, hi) \
    asm("cvt.rn.f16x2.f32 %0, %1, %2;" : "=r"(d) : "f"(hi), "f"(lo))

__device__ __forceinline__ float f16_rt(float v) {
    float r;
    asm("{ .reg .f16 t; cvt.rn.f16.f32 t, %1; cvt.f32.f16 %0, t; }" : "=f"(r) : "f"(v));
    return r;
}
__device__ __forceinline__ float lo_res(float v) { return v - f16_rt(v); }

__device__ __forceinline__ void mma_f16(float* d, uint4 a, uint2 b) {
    asm volatile(
        "mma.sync.aligned.m16n8k16.row.col.f32.f16.f16.f32 "
        "{%0,%1,%2,%3},{%4,%5,%6,%7},{%8,%9},{%0,%1,%2,%3};"
        : "+f"(d[0]), "+f"(d[1]), "+f"(d[2]), "+f"(d[3])
        : "r"(a.x), "r"(a.y), "r"(a.z), "r"(a.w), "r"(b.x), "r"(b.y));
}

#define CP_ASYNC16(dst, src) \
    asm volatile("cp.async.cg.shared.global [%0], [%1], 16;" :: "r"(dst), "l"(src))
#define CP_COMMIT()  asm volatile("cp.async.commit_group;" ::: "memory")
#define CP_WAIT(n)   asm volatile("cp.async.wait_group %0;" :: "n"(n) : "memory")
#define BARG(id)     asm volatile("bar.sync %0, 128;" :: "r"(id) : "memory")
#define LDS128(v, addr) \
    asm volatile("ld.shared.v4.b32 {%0,%1,%2,%3}, [%4];" \
        : "=r"((v).x), "=r"((v).y), "=r"((v).z), "=r"((v).w) : "r"(addr))
#define LDS64F(x, y, addr) \
    asm volatile("ld.shared.v2.f32 {%0,%1}, [%2];" : "=f"(x), "=f"(y) : "r"(addr))

__device__ __forceinline__ uint32_t smem_u32(const void* p) {
    uint32_t a;
    asm("{ .reg .u64 t; cvta.to.shared.u64 t, %1; cvt.u32.u64 %0, t; }" : "=r"(a) : "l"(p));
    return a;
}

// ---------------- pre-kernel: fp16 hi/lo splits of E (32-token subtiles) + halfE2 ----------------
__global__ void pre_kernel(const float* __restrict__ e) {
    const int sub = blockIdx.x;          // 0..31
    const int tid = threadIdx.x;         // 256 threads, one fragment position each
    char* base = (char*)&g_B[sub][0];

    {
        int lane = tid & 31;
        int pr   = (tid >> 5) & 1;
        int ks   = tid >> 6;             // 0..3
        int c = lane & 3, nq = lane >> 2;
        int k0 = ks * 16 + 2 * c;
        uint32_t hi[4], lo[4];
#pragma unroll
        for (int s = 0; s < 2; s++) {
            int tok = sub * 32 + (pr * 2 + s) * 8 + nq;
            const float* row = e + (size_t)tok * EMB;
            float v0 = row[k0], v1 = row[k0 + 1], v2 = row[k0 + 8], v3 = row[k0 + 9];
            PACKH(hi[s * 2 + 0], v0, v1);
            PACKH(hi[s * 2 + 1], v2, v3);
            PACKH(lo[s * 2 + 0], lo_res(v0), lo_res(v1));
            PACKH(lo[s * 2 + 1], lo_res(v2), lo_res(v3));
        }
        int off = ks * 1024 + pr * 512 + lane * 16;
        *(uint4*)(base + off)        = make_uint4(hi[0], hi[1], hi[2], hi[3]);
        *(uint4*)(base + 4096 + off) = make_uint4(lo[0], lo[1], lo[2], lo[3]);
    }

    if (tid < 32) {
        int tok = sub * 32 + tid;
        const float* row = e + (size_t)tok * EMB;
        float h = 0.f;
#pragma unroll
        for (int kk = 0; kk < EMB; kk++) h += row[kk] * row[kk];
        g_hE2[tok] = 0.5f * h;
    }
}

// ---------------- SMEM layout (bytes) ----------------
#define SM_A     0                        // 32768
#define SM_ST    32768                    // 4 stage buffers * 8192 = 32768
#define SM_HE2   65536                    // 4096
#define SM_REDS  69632                    // 128*2 floats
#define SM_REDI  70656
#define SM_QIDX  71680
#define SM_TOTAL 72192                    // 70.5 KB -> 2 CTAs/SM

#define LOAD_A(A, ksn) \
    LDS128(A[0], a0base + (ksn) * 512u); \
    LDS128(A[1], a0base + 2048u + (ksn) * 512u); \
    LDS128(A[2], a1base + (ksn) * 512u); \
    LDS128(A[3], a1base + 2048u + (ksn) * 512u)

#define LOAD_B0(B0, ksn) \
    LDS128(B0[0], bpair + (ksn) * 1024u); \
    LDS128(B0[1], bpair + (ksn) * 1024u + 512u)

#define LOAD_B1(B1, ksn) \
    LDS128(B1[0], bpair + 4096u + (ksn) * 1024u); \
    LDS128(B1[1], bpair + 4096u + (ksn) * 1024u + 512u)

#define PASSX(Am0, Am1, B) do { \
    uint2 _b; \
    _b = make_uint2(B[0].x, B[0].y); mma_f16(&acc[0],  Am0, _b); mma_f16(&acc[16], Am1, _b); \
    _b = make_uint2(B[0].z, B[0].w); mma_f16(&acc[4],  Am0, _b); mma_f16(&acc[20], Am1, _b); \
    _b = make_uint2(B[1].x, B[1].y); mma_f16(&acc[8],  Am0, _b); mma_f16(&acc[24], Am1, _b); \
    _b = make_uint2(B[1].z, B[1].w); mma_f16(&acc[12], Am0, _b); mma_f16(&acc[28], Am1, _b); \
} while (0)

// 3 products: X0E0, X0E1, X1E0
#define STEP(A, B0, B1, An, B0n, B1n, KSN) \
    PASSX(A[0], A[1], B0); \
    LOAD_A(An, KSN); \
    PASSX(A[0], A[1], B1); \
    LOAD_B0(B0n, KSN); \
    PASSX(A[2], A[3], B0); \
    LOAD_B1(B1n, KSN)

#define STEP_LAST(A, B0, B1) \
    PASSX(A[0], A[1], B0); \
    PASSX(A[0], A[1], B1); \
    PASSX(A[2], A[3], B0)

__global__ __launch_bounds__(NTHREADS, 2) void vq_kernel(
    const float* __restrict__ x,      // [B, EMB, CODES]
    const float* __restrict__ e,      // [NT, EMB]
    float* __restrict__ xout,
    float* __restrict__ idxout)
{
    extern __shared__ uint8_t sm[];
    const uint32_t smb = smem_u32(sm);
    const int tid  = threadIdx.x;
    const int warp = tid >> 5;
    const int lane = tid & 31;
    const int grp  = warp >> 2;       // 0: tokens 0-511, 1: 512-1023
    const int mw   = warp & 3;        // rows mw*32 .. +31
    const int gtid = tid & 127;
    const int b    = blockIdx.y;
    const int c0   = blockIdx.x * QB;

    const uint32_t st_base = smb + SM_ST + (uint32_t)grp * 2u * SUB_BYTES;

    // ---- cp.async prologue: subtiles grp*16, grp*16+1 ----
#pragma unroll
    for (int st = 0; st < 2; st++) {
        const char* src = (const char*)&g_B[grp * NSTG + st][0];
        uint32_t dst = st_base + st * SUB_BYTES;
#pragma unroll
        for (int it = 0; it < 4; it++) {
            int off = it * 128 * 16 + gtid * 16;
            CP_ASYNC16(dst + off, src + off);
        }
        CP_COMMIT();
    }

    // ---- pack A fragments: fp16 hi/lo of x[b][k][c0+r] ----
    const float* xb = x + (size_t)b * EMB * CODES + c0;
    for (int p = tid; p < 1024; p += NTHREADS) {
        int ln = p & 31;
        int ks = (p >> 5) & 3;
        int ms = (p >> 7) & 1;
        int w  = p >> 8;
        int r  = w * 32 + ms * 16 + (ln >> 2);
        int c  = ln & 3;
        int k0 = ks * 16 + 2 * c;
        float v00 = xb[(size_t)k0 * CODES + r];
        float v01 = xb[(size_t)(k0 + 1) * CODES + r];
        float v02 = xb[(size_t)(k0 + 8) * CODES + r];
        float v03 = xb[(size_t)(k0 + 9) * CODES + r];
        float v10 = xb[(size_t)k0 * CODES + r + 8];
        float v11 = xb[(size_t)(k0 + 1) * CODES + r + 8];
        float v12 = xb[(size_t)(k0 + 8) * CODES + r + 8];
        float v13 = xb[(size_t)(k0 + 9) * CODES + r + 8];
        uint32_t a0, a1, a2, a3, l0, l1, l2, l3;
        PACKH(a0, v00, v01); PACKH(a1, v10, v11);
        PACKH(a2, v02, v03); PACKH(a3, v12, v13);
        PACKH(l0, lo_res(v00), lo_res(v01)); PACKH(l1, lo_res(v10), lo_res(v11));
        PACKH(l2, lo_res(v02), lo_res(v03)); PACKH(l3, lo_res(v12), lo_res(v13));
        int off = w * 4096 + ms * 2048 + ks * 512 + ln * 16;
        *(uint4*)(sm + SM_A + off)          = make_uint4(a0, a1, a2, a3);
        *(uint4*)(sm + SM_A + 16384 + off)  = make_uint4(l0, l1, l2, l3);
    }
    // ---- halfE2 table into smem ----
    float* hE2s = (float*)(sm + SM_HE2);
    for (int i = tid; i < NT; i += NTHREADS) hE2s[i] = g_hE2[i];
    __syncthreads();

    float best[4];
    int   bidx[4];
#pragma unroll
    for (int s = 0; s < 4; s++) { best[s] = -3.0e38f; bidx[s] = 0; }

    const uint32_t a0base = smb + SM_A + (uint32_t)mw * 4096u + (uint32_t)lane * 16u;
    const uint32_t a1base = a0base + 16384u;
    const int barid = 1 + grp;
    const uint32_t hlane = smb + SM_HE2 + (uint32_t)(lane & 3) * 8u;

    for (int st = 0; st < NSTG; st++) {
        if (st < NSTG - 2) { CP_WAIT(1); } else { CP_WAIT(0); }
        BARG(barid);

        const uint32_t sb = st_base + (uint32_t)(st & 1) * SUB_BYTES;
        const uint32_t bpair = sb + (uint32_t)lane * 16u;
        float acc[32];
#pragma unroll
        for (int z = 0; z < 32; z++) acc[z] = 0.f;

        uint4 Xa[4], Ya[2], Za[2];
        uint4 Xb[4], Yb[2], Zb[2];
        LOAD_A(Xa, 0);
        LOAD_B0(Ya, 0);
        LOAD_B1(Za, 0);
        STEP(Xa, Ya, Za, Xb, Yb, Zb, 1);
        STEP(Xb, Yb, Zb, Xa, Ya, Za, 2);
        STEP(Xa, Ya, Za, Xb, Yb, Zb, 3);
        STEP_LAST(Xb, Yb, Zb);

        // ---- epilogue: exact fp32 h-subtract + register argmax ----
        const int tbase = (grp * NSTG + st) * 32;
#pragma unroll
        for (int n = 0; n < 4; n++) {
            int tokb = tbase + n * 8 + (lane & 3) * 2;
            float h0, h1;
            LDS64F(h0, h1, hlane + (uint32_t)(tbase + n * 8) * 4u);
#pragma unroll
            for (int ms = 0; ms < 2; ms++) {
                const float* d = &acc[(ms * 4 + n) * 4];
                float v0 = d[0] - h0;
                float v1 = d[1] - h1;
                float v2 = d[2] - h0;
                float v3 = d[3] - h1;
                int s0 = ms * 2;
                if (v0 > best[s0])     { best[s0] = v0;     bidx[s0] = tokb; }
                if (v1 > best[s0])     { best[s0] = v1;     bidx[s0] = tokb + 1; }
                if (v2 > best[s0 + 1]) { best[s0 + 1] = v2; bidx[s0 + 1] = tokb; }
                if (v3 > best[s0 + 1]) { best[s0 + 1] = v3; bidx[s0 + 1] = tokb + 1; }
            }
        }

        BARG(barid);
        if (st + 2 < NSTG) {
            const char* src = (const char*)&g_B[grp * NSTG + st + 2][0];
            uint32_t dst = st_base + (uint32_t)(st & 1) * SUB_BYTES;
#pragma unroll
            for (int it = 0; it < 4; it++) {
                int off = it * 128 * 16 + gtid * 16;
                CP_ASYNC16(dst + off, src + off);
            }
            CP_COMMIT();
        }
    }

    // ---- merge across the 4 lanes sharing each row ----
#pragma unroll
    for (int s = 0; s < 4; s++) {
#pragma unroll
        for (int off = 1; off <= 2; off <<= 1) {
            float os = __shfl_xor_sync(0xffffffffu, best[s], off);
            int   oi = __shfl_xor_sync(0xffffffffu, bidx[s], off);
            if (os > best[s] || (os == best[s] && oi < bidx[s])) {
                best[s] = os; bidx[s] = oi;
            }
        }
    }

    float* REDS = (float*)(sm + SM_REDS);
    int*   REDI = (int*)(sm + SM_REDI);
    int*   QIDX = (int*)(sm + SM_QIDX);
    if ((lane & 3) == 0) {
        // rows: mw*32 + ms*16 + (lane>>2) + (s&1)*8, s = ms*2 + rr
#pragma unroll
        for (int s = 0; s < 4; s++) {
            int row = mw * 32 + (s >> 1) * 16 + (lane >> 2) + (s & 1) * 8;
            REDS[row * 2 + grp] = best[s];
            REDI[row * 2 + grp] = bidx[s];
        }
    }
    __syncthreads();

    if (tid < QB) {
        float s0 = REDS[tid * 2], s1 = REDS[tid * 2 + 1];
        int   i0 = REDI[tid * 2], i1 = REDI[tid * 2 + 1];
        int bi = (s1 > s0) ? i1 : i0;   // group0 indices lower; tie -> i0
        QIDX[tid] = bi;
        idxout[(size_t)b * CODES + c0 + tid] = (float)bi;
    }
    __syncthreads();

    // ---- gather x_out ----
#pragma unroll
    for (int it = 0; it < (EMB * QB) / NTHREADS; ++it) {
        int idx = it * NTHREADS + tid;
        int q = idx & (QB - 1);
        int j = idx >> 7;
        xout[(size_t)b * EMB * CODES + (size_t)j * CODES + c0 + q] =
            e[(size_t)QIDX[q] * EMB + j];
    }
}

extern "C" void kernel_launch(void* const* d_in, const int* in_sizes, int n_in,
                              void* d_out, int out_size) {
    const float* x = (const float*)d_in[0];   // [16, 64, 16384]
    const float* e = (const float*)d_in[1];   // [1024, 64]
    int B = in_sizes[0] / (EMB * CODES);

    float* xout   = (float*)d_out;
    float* idxout = xout + (size_t)B * EMB * CODES;

    pre_kernel<<<NSUB, 256>>>(e);

    cudaFuncSetAttribute(vq_kernel, cudaFuncAttributeMaxDynamicSharedMemorySize, SM_TOTAL);
    dim3 grid(CODES / QB, B);
    vq_kernel<<<grid, NTHREADS, SM_TOTAL>>>(x, e, xout, idxout);
}

// round 15
// speedup vs baseline: 2.3543x; 1.0031x over previous
#include <cuda_runtime.h>
#include <cuda_fp16.h>
#include <cstdint>

#define EMB      64
#define CODES    16384
#define NT       1024
#define QB       128
#define NTHREADS 256
#define NSUB     16          // 16 subtiles of 64 tokens
#define NSTG     8           // subtiles per group

// per 64-token subtile: [split2][ks4][npair4][lane32][16B] = 16384 B
#define SUB_BYTES  16384
#define SUB_FLOATS (SUB_BYTES / 4)
__device__ float g_B[NSUB][SUB_FLOATS];
__device__ float g_hE2[NT];

#define PACKH(d, lo, hi) \
    asm("cvt.rn.f16x2.f32 %0, %1, %2;" : "=r"(d) : "f"(hi), "f"(lo))

__device__ __forceinline__ float f16_rt(float v) {
    float r;
    asm("{ .reg .f16 t; cvt.rn.f16.f32 t, %1; cvt.f32.f16 %0, t; }" : "=f"(r) : "f"(v));
    return r;
}
__device__ __forceinline__ float lo_res(float v) { return v - f16_rt(v); }

__device__ __forceinline__ void mma_f16(float* d, uint4 a, uint2 b) {
    asm volatile(
        "mma.sync.aligned.m16n8k16.row.col.f32.f16.f16.f32 "
        "{%0,%1,%2,%3},{%4,%5,%6,%7},{%8,%9},{%0,%1,%2,%3};"
        : "+f"(d[0]), "+f"(d[1]), "+f"(d[2]), "+f"(d[3])
        : "r"(a.x), "r"(a.y), "r"(a.z), "r"(a.w), "r"(b.x), "r"(b.y));
}

#define CP_ASYNC16(dst, src) \
    asm volatile("cp.async.cg.shared.global [%0], [%1], 16;" :: "r"(dst), "l"(src))
#define CP_COMMIT()  asm volatile("cp.async.commit_group;" ::: "memory")
#define CP_WAIT(n)   asm volatile("cp.async.wait_group %0;" :: "n"(n) : "memory")
#define BARG(id)     asm volatile("bar.sync %0, 128;" :: "r"(id) : "memory")
#define LDS128(v, addr) \
    asm volatile("ld.shared.v4.b32 {%0,%1,%2,%3}, [%4];" \
        : "=r"((v).x), "=r"((v).y), "=r"((v).z), "=r"((v).w) : "r"(addr))
#define LDS64F(x, y, addr) \
    asm volatile("ld.shared.v2.f32 {%0,%1}, [%2];" : "=f"(x), "=f"(y) : "r"(addr))

__device__ __forceinline__ uint32_t smem_u32(const void* p) {
    uint32_t a;
    asm("{ .reg .u64 t; cvta.to.shared.u64 t, %1; cvt.u32.u64 %0, t; }" : "=r"(a) : "l"(p));
    return a;
}

// ---------------- pre-kernel: fp16 hi/lo splits of E (64-token subtiles) + halfE2 ----------------
__global__ void pre_kernel(const float* __restrict__ e) {
    const int sub = blockIdx.x;
    const int tid = threadIdx.x;
    char* base = (char*)&g_B[sub][0];

    // product region: ks4 * npair4 * lane32 = 512 positions; uint4 = {b0,b1} of 2 n-tiles
    for (int pos = tid; pos < 512; pos += blockDim.x) {
        int lane = pos & 31;
        int pr   = (pos >> 5) & 3;
        int ks   = pos >> 7;
        int c = lane & 3, nq = lane >> 2;
        int k0 = ks * 16 + 2 * c;
        uint32_t hi[4], lo[4];
#pragma unroll
        for (int s = 0; s < 2; s++) {
            int tok = sub * 64 + (pr * 2 + s) * 8 + nq;
            const float* row = e + (size_t)tok * EMB;
            float v0 = row[k0], v1 = row[k0 + 1], v2 = row[k0 + 8], v3 = row[k0 + 9];
            PACKH(hi[s * 2 + 0], v0, v1);
            PACKH(hi[s * 2 + 1], v2, v3);
            PACKH(lo[s * 2 + 0], lo_res(v0), lo_res(v1));
            PACKH(lo[s * 2 + 1], lo_res(v2), lo_res(v3));
        }
        int off = ks * 2048 + pr * 512 + lane * 16;
        *(uint4*)(base + off)        = make_uint4(hi[0], hi[1], hi[2], hi[3]);
        *(uint4*)(base + 8192 + off) = make_uint4(lo[0], lo[1], lo[2], lo[3]);
    }

    if (tid < 64) {
        int tok = sub * 64 + tid;
        const float* row = e + (size_t)tok * EMB;
        float h = 0.f;
#pragma unroll
        for (int kk = 0; kk < EMB; kk++) h += row[kk] * row[kk];
        g_hE2[tok] = 0.5f * h;
    }
}

// ---------------- SMEM layout (bytes) ----------------
#define SM_A     0                        // 32768
#define SM_ST    32768                    // 4 stage buffers * 16384 = 65536
#define SM_HE2   98304                    // 4096
#define SM_REDS  102400                   // 128*2 floats
#define SM_REDI  103424
#define SM_QIDX  104448
#define SM_TOTAL 104960                   // 102.5 KB -> 2 CTAs/SM (regs are the cap)

#define LOAD_A(A, ksn) \
    LDS128(A[0], a0base + (ksn) * 512u); \
    LDS128(A[1], a0base + 2048u + (ksn) * 512u); \
    LDS128(A[2], a1base + (ksn) * 512u); \
    LDS128(A[3], a1base + 2048u + (ksn) * 512u)

#define LOAD_B0(B0, ksn) \
    LDS128(B0[0], bpair + (ksn) * 2048u); \
    LDS128(B0[1], bpair + (ksn) * 2048u + 512u); \
    LDS128(B0[2], bpair + (ksn) * 2048u + 1024u); \
    LDS128(B0[3], bpair + (ksn) * 2048u + 1536u)

#define LOAD_B1(B1, ksn) \
    LDS128(B1[0], bpair + 8192u + (ksn) * 2048u); \
    LDS128(B1[1], bpair + 8192u + (ksn) * 2048u + 512u); \
    LDS128(B1[2], bpair + 8192u + (ksn) * 2048u + 1024u); \
    LDS128(B1[3], bpair + 8192u + (ksn) * 2048u + 1536u)

#define PASSX8(Am0, Am1, B) do { \
    uint2 _b; \
    _b = make_uint2(B[0].x, B[0].y); mma_f16(&acc[0],  Am0, _b); mma_f16(&acc[32], Am1, _b); \
    _b = make_uint2(B[0].z, B[0].w); mma_f16(&acc[4],  Am0, _b); mma_f16(&acc[36], Am1, _b); \
    _b = make_uint2(B[1].x, B[1].y); mma_f16(&acc[8],  Am0, _b); mma_f16(&acc[40], Am1, _b); \
    _b = make_uint2(B[1].z, B[1].w); mma_f16(&acc[12], Am0, _b); mma_f16(&acc[44], Am1, _b); \
    _b = make_uint2(B[2].x, B[2].y); mma_f16(&acc[16], Am0, _b); mma_f16(&acc[48], Am1, _b); \
    _b = make_uint2(B[2].z, B[2].w); mma_f16(&acc[20], Am0, _b); mma_f16(&acc[52], Am1, _b); \
    _b = make_uint2(B[3].x, B[3].y); mma_f16(&acc[24], Am0, _b); mma_f16(&acc[56], Am1, _b); \
    _b = make_uint2(B[3].z, B[3].w); mma_f16(&acc[28], Am0, _b); mma_f16(&acc[60], Am1, _b); \
} while (0)

// 3 products per ks, single-buffered fragments (occupancy hides latency)
#define STEP(KSN) do { \
    uint4 A[4], B0[4], B1[4]; \
    LOAD_A(A, KSN); \
    LOAD_B0(B0, KSN); \
    PASSX8(A[0], A[1], B0); \
    LOAD_B1(B1, KSN); \
    PASSX8(A[0], A[1], B1); \
    PASSX8(A[2], A[3], B0); \
} while (0)

__global__ __launch_bounds__(NTHREADS, 2) void vq_kernel(
    const float* __restrict__ x,      // [B, EMB, CODES]
    const float* __restrict__ e,      // [NT, EMB]
    float* __restrict__ xout,
    float* __restrict__ idxout)
{
    extern __shared__ uint8_t sm[];
    const uint32_t smb = smem_u32(sm);
    const int tid  = threadIdx.x;
    const int warp = tid >> 5;
    const int lane = tid & 31;
    const int grp  = warp >> 2;       // 0: tokens 0-511, 1: 512-1023
    const int mw   = warp & 3;        // rows mw*32 .. +31
    const int gtid = tid & 127;
    const int b    = blockIdx.y;
    const int c0   = blockIdx.x * QB;

    const uint32_t st_base = smb + SM_ST + (uint32_t)grp * 2u * SUB_BYTES;

    // ---- cp.async prologue: subtiles grp*8, grp*8+1 ----
#pragma unroll
    for (int st = 0; st < 2; st++) {
        const char* src = (const char*)&g_B[grp * NSTG + st][0];
        uint32_t dst = st_base + st * SUB_BYTES;
#pragma unroll
        for (int it = 0; it < 8; it++) {
            int off = it * 128 * 16 + gtid * 16;
            CP_ASYNC16(dst + off, src + off);
        }
        CP_COMMIT();
    }

    // ---- pack A fragments: fp16 hi/lo of x[b][k][c0+r] ----
    const float* xb = x + (size_t)b * EMB * CODES + c0;
    for (int p = tid; p < 1024; p += NTHREADS) {
        int ln = p & 31;
        int ks = (p >> 5) & 3;
        int ms = (p >> 7) & 1;
        int w  = p >> 8;
        int r  = w * 32 + ms * 16 + (ln >> 2);
        int c  = ln & 3;
        int k0 = ks * 16 + 2 * c;
        float v00 = xb[(size_t)k0 * CODES + r];
        float v01 = xb[(size_t)(k0 + 1) * CODES + r];
        float v02 = xb[(size_t)(k0 + 8) * CODES + r];
        float v03 = xb[(size_t)(k0 + 9) * CODES + r];
        float v10 = xb[(size_t)k0 * CODES + r + 8];
        float v11 = xb[(size_t)(k0 + 1) * CODES + r + 8];
        float v12 = xb[(size_t)(k0 + 8) * CODES + r + 8];
        float v13 = xb[(size_t)(k0 + 9) * CODES + r + 8];
        uint32_t a0, a1, a2, a3, l0, l1, l2, l3;
        PACKH(a0, v00, v01); PACKH(a1, v10, v11);
        PACKH(a2, v02, v03); PACKH(a3, v12, v13);
        PACKH(l0, lo_res(v00), lo_res(v01)); PACKH(l1, lo_res(v10), lo_res(v11));
        PACKH(l2, lo_res(v02), lo_res(v03)); PACKH(l3, lo_res(v12), lo_res(v13));
        int off = w * 4096 + ms * 2048 + ks * 512 + ln * 16;
        *(uint4*)(sm + SM_A + off)          = make_uint4(a0, a1, a2, a3);
        *(uint4*)(sm + SM_A + 16384 + off)  = make_uint4(l0, l1, l2, l3);
    }
    float* hE2s = (float*)(sm + SM_HE2);
    for (int i = tid; i < NT; i += NTHREADS) hE2s[i] = g_hE2[i];
    __syncthreads();

    float best[4];
    int   bidx[4];
#pragma unroll
    for (int s = 0; s < 4; s++) { best[s] = -3.0e38f; bidx[s] = 0; }

    const uint32_t a0base = smb + SM_A + (uint32_t)mw * 4096u + (uint32_t)lane * 16u;
    const uint32_t a1base = a0base + 16384u;
    const int barid = 1 + grp;
    const uint32_t hlane = smb + SM_HE2 + (uint32_t)(lane & 3) * 8u;

    for (int st = 0; st < NSTG; st++) {
        if (st < NSTG - 2) { CP_WAIT(1); } else { CP_WAIT(0); }
        BARG(barid);

        const uint32_t sb = st_base + (uint32_t)(st & 1) * SUB_BYTES;
        const uint32_t bpair = sb + (uint32_t)lane * 16u;
        float acc[64];
#pragma unroll
        for (int z = 0; z < 64; z++) acc[z] = 0.f;

        STEP(0);
        STEP(1);
        STEP(2);
        STEP(3);

        // ---- epilogue: exact fp32 h-subtract + register argmax ----
        const int tbase = (grp * NSTG + st) * 64;
#pragma unroll
        for (int n = 0; n < 8; n++) {
            int tokb = tbase + n * 8 + (lane & 3) * 2;
            float h0, h1;
            LDS64F(h0, h1, hlane + (uint32_t)(tbase + n * 8) * 4u);
#pragma unroll
            for (int ms = 0; ms < 2; ms++) {
                const float* d = &acc[(ms * 8 + n) * 4];
                float v0 = d[0] - h0;
                float v1 = d[1] - h1;
                float v2 = d[2] - h0;
                float v3 = d[3] - h1;
                int s0 = ms * 2;
                if (v0 > best[s0])     { best[s0] = v0;     bidx[s0] = tokb; }
                if (v1 > best[s0])     { best[s0] = v1;     bidx[s0] = tokb + 1; }
                if (v2 > best[s0 + 1]) { best[s0 + 1] = v2; bidx[s0 + 1] = tokb; }
                if (v3 > best[s0 + 1]) { best[s0 + 1] = v3; bidx[s0 + 1] = tokb + 1; }
            }
        }

        BARG(barid);
        if (st + 2 < NSTG) {
            const char* src = (const char*)&g_B[grp * NSTG + st + 2][0];
            uint32_t dst = st_base + (uint32_t)(st & 1) * SUB_BYTES;
#pragma unroll
            for (int it = 0; it < 8; it++) {
                int off = it * 128 * 16 + gtid * 16;
                CP_ASYNC16(dst + off, src + off);
            }
            CP_COMMIT();
        }
    }

    // ---- merge across the 4 lanes sharing each row ----
#pragma unroll
    for (int s = 0; s < 4; s++) {
#pragma unroll
        for (int off = 1; off <= 2; off <<= 1) {
            float os = __shfl_xor_sync(0xffffffffu, best[s], off);
            int   oi = __shfl_xor_sync(0xffffffffu, bidx[s], off);
            if (os > best[s] || (os == best[s] && oi < bidx[s])) {
                best[s] = os; bidx[s] = oi;
            }
        }
    }

    float* REDS = (float*)(sm + SM_REDS);
    int*   REDI = (int*)(sm + SM_REDI);
    int*   QIDX = (int*)(sm + SM_QIDX);
    if ((lane & 3) == 0) {
#pragma unroll
        for (int s = 0; s < 4; s++) {
            int row = mw * 32 + (s >> 1) * 16 + (lane >> 2) + (s & 1) * 8;
            REDS[row * 2 + grp] = best[s];
            REDI[row * 2 + grp] = bidx[s];
        }
    }
    __syncthreads();

    if (tid < QB) {
        float s0 = REDS[tid * 2], s1 = REDS[tid * 2 + 1];
        int   i0 = REDI[tid * 2], i1 = REDI[tid * 2 + 1];
        int bi = (s1 > s0) ? i1 : i0;   // group0 indices lower; tie -> i0
        QIDX[tid] = bi;
        idxout[(size_t)b * CODES + c0 + tid] = (float)bi;
    }
    __syncthreads();

    // ---- gather x_out ----
#pragma unroll
    for (int it = 0; it < (EMB * QB) / NTHREADS; ++it) {
        int idx = it * NTHREADS + tid;
        int q = idx & (QB - 1);
        int j = idx >> 7;
        xout[(size_t)b * EMB * CODES + (size_t)j * CODES + c0 + q] =
            e[(size_t)QIDX[q] * EMB + j];
    }
}

extern "C" void kernel_launch(void* const* d_in, const int* in_sizes, int n_in,
                              void* d_out, int out_size) {
    const float* x = (const float*)d_in[0];   // [16, 64, 16384]
    const float* e = (const float*)d_in[1];   // [1024, 64]
    int B = in_sizes[0] / (EMB * CODES);

    float* xout   = (float*)d_out;
    float* idxout = xout + (size_t)B * EMB * CODES;

    pre_kernel<<<NSUB, 256>>>(e);

    cudaFuncSetAttribute(vq_kernel, cudaFuncAttributeMaxDynamicSharedMemorySize, SM_TOTAL);
    dim3 grid(CODES / QB, B);
    vq_kernel<<<grid, NTHREADS, SM_TOTAL>>>(x, e, xout, idxout);
}

// round 16
// speedup vs baseline: 2.4982x; 1.0611x over previous
#include <cuda_runtime.h>
#include <cuda_fp16.h>
#include <cstdint>

#define EMB      64
#define CODES    16384
#define NT       1024
#define QB       128
#define NTHREADS 256
#define NSUB     32          // 32 subtiles of 32 tokens
#define NSTG     16          // subtiles per group

// per 32-token subtile: [split2][ks4][pair2][lane32][uint4] = 8192 B
#define SUB_BYTES  8192
#define SUB_FLOATS (SUB_BYTES / 4)
__device__ float g_B[NSUB][SUB_FLOATS];
__device__ float g_hE2[NT];

#define PACKH(d, lo, hi) \
    asm("cvt.rn.f16x2.f32 %0, %1, %2;" : "=r"(d) : "f"(hi), "f"(lo))

__device__ __forceinline__ float f16_rt(float v) {
    float r;
    asm("{ .reg .f16 t; cvt.rn.f16.f32 t, %1; cvt.f32.f16 %0, t; }" : "=f"(r) : "f"(v));
    return r;
}
__device__ __forceinline__ float lo_res(float v) { return v - f16_rt(v); }

__device__ __forceinline__ void mma_f16(float* d, uint4 a, uint2 b) {
    asm volatile(
        "mma.sync.aligned.m16n8k16.row.col.f32.f16.f16.f32 "
        "{%0,%1,%2,%3},{%4,%5,%6,%7},{%8,%9},{%0,%1,%2,%3};"
        : "+f"(d[0]), "+f"(d[1]), "+f"(d[2]), "+f"(d[3])
        : "r"(a.x), "r"(a.y), "r"(a.z), "r"(a.w), "r"(b.x), "r"(b.y));
}

#define CP_ASYNC16(dst, src) \
    asm volatile("cp.async.cg.shared.global [%0], [%1], 16;" :: "r"(dst), "l"(src))
#define CP_COMMIT()  asm volatile("cp.async.commit_group;" ::: "memory")
#define CP_WAIT(n)   asm volatile("cp.async.wait_group %0;" :: "n"(n) : "memory")
#define BARG(id)     asm volatile("bar.sync %0, 128;" :: "r"(id) : "memory")
#define LDS128(v, addr) \
    asm volatile("ld.shared.v4.b32 {%0,%1,%2,%3}, [%4];" \
        : "=r"((v).x), "=r"((v).y), "=r"((v).z), "=r"((v).w) : "r"(addr))
#define LDS64F(x, y, addr) \
    asm volatile("ld.shared.v2.f32 {%0,%1}, [%2];" : "=f"(x), "=f"(y) : "r"(addr))

__device__ __forceinline__ uint32_t smem_u32(const void* p) {
    uint32_t a;
    asm("{ .reg .u64 t; cvta.to.shared.u64 t, %1; cvt.u32.u64 %0, t; }" : "=r"(a) : "l"(p));
    return a;
}

// ---------------- pre-kernel: fp16 hi/lo splits of E (32-token subtiles) + halfE2 ----------------
__global__ void pre_kernel(const float* __restrict__ e) {
    const int sub = blockIdx.x;          // 0..31
    const int tid = threadIdx.x;         // 256 threads, one fragment position each
    char* base = (char*)&g_B[sub][0];

    {
        int lane = tid & 31;
        int pr   = (tid >> 5) & 1;
        int ks   = tid >> 6;             // 0..3
        int c = lane & 3, nq = lane >> 2;
        int k0 = ks * 16 + 2 * c;
        uint32_t hi[4], lo[4];
#pragma unroll
        for (int s = 0; s < 2; s++) {
            int tok = sub * 32 + (pr * 2 + s) * 8 + nq;
            const float* row = e + (size_t)tok * EMB;
            float v0 = row[k0], v1 = row[k0 + 1], v2 = row[k0 + 8], v3 = row[k0 + 9];
            PACKH(hi[s * 2 + 0], v0, v1);
            PACKH(hi[s * 2 + 1], v2, v3);
            PACKH(lo[s * 2 + 0], lo_res(v0), lo_res(v1));
            PACKH(lo[s * 2 + 1], lo_res(v2), lo_res(v3));
        }
        int off = ks * 1024 + pr * 512 + lane * 16;
        *(uint4*)(base + off)        = make_uint4(hi[0], hi[1], hi[2], hi[3]);
        *(uint4*)(base + 4096 + off) = make_uint4(lo[0], lo[1], lo[2], lo[3]);
    }

    if (tid < 32) {
        int tok = sub * 32 + tid;
        const float* row = e + (size_t)tok * EMB;
        float h = 0.f;
#pragma unroll
        for (int kk = 0; kk < EMB; kk++) h += row[kk] * row[kk];
        g_hE2[tok] = 0.5f * h;
    }
}

// ---------------- SMEM layout (bytes) ----------------
#define SM_A     0                        // 32768
#define SM_ST    32768                    // 4 stage buffers * 8192 = 32768
#define SM_HE2   65536                    // 4096
#define SM_REDS  69632                    // 128*2 floats
#define SM_REDI  70656
#define SM_QIDX  71680
#define SM_TOTAL 72192                    // 70.5 KB -> 3 CTAs/SM (211.5 <= 228)

#define LOAD_A(A, ksn) \
    LDS128(A[0], a0base + (ksn) * 512u); \
    LDS128(A[1], a0base + 2048u + (ksn) * 512u); \
    LDS128(A[2], a1base + (ksn) * 512u); \
    LDS128(A[3], a1base + 2048u + (ksn) * 512u)

#define LOAD_B0(B0, ksn) \
    LDS128(B0[0], bpair + (ksn) * 1024u); \
    LDS128(B0[1], bpair + (ksn) * 1024u + 512u)

#define LOAD_B1(B1, ksn) \
    LDS128(B1[0], bpair + 4096u + (ksn) * 1024u); \
    LDS128(B1[1], bpair + 4096u + (ksn) * 1024u + 512u)

#define PASSX(Am0, Am1, B) do { \
    uint2 _b; \
    _b = make_uint2(B[0].x, B[0].y); mma_f16(&acc[0],  Am0, _b); mma_f16(&acc[16], Am1, _b); \
    _b = make_uint2(B[0].z, B[0].w); mma_f16(&acc[4],  Am0, _b); mma_f16(&acc[20], Am1, _b); \
    _b = make_uint2(B[1].x, B[1].y); mma_f16(&acc[8],  Am0, _b); mma_f16(&acc[24], Am1, _b); \
    _b = make_uint2(B[1].z, B[1].w); mma_f16(&acc[12], Am0, _b); mma_f16(&acc[28], Am1, _b); \
} while (0)

// 3 products: X0E0, X0E1, X1E0, single-buffered fragments
#define STEP(KSN) do { \
    uint4 A[4], B0[2], B1[2]; \
    LOAD_A(A, KSN); \
    LOAD_B0(B0, KSN); \
    PASSX(A[0], A[1], B0); \
    LOAD_B1(B1, KSN); \
    PASSX(A[0], A[1], B1); \
    PASSX(A[2], A[3], B0); \
} while (0)

__global__ __launch_bounds__(NTHREADS, 3) void vq_kernel(
    const float* __restrict__ x,      // [B, EMB, CODES]
    const float* __restrict__ e,      // [NT, EMB]
    float* __restrict__ xout,
    float* __restrict__ idxout)
{
    extern __shared__ uint8_t sm[];
    const uint32_t smb = smem_u32(sm);
    const int tid  = threadIdx.x;
    const int warp = tid >> 5;
    const int lane = tid & 31;
    const int grp  = warp >> 2;       // 0: tokens 0-511, 1: 512-1023
    const int mw   = warp & 3;        // rows mw*32 .. +31
    const int gtid = tid & 127;
    const int b    = blockIdx.y;
    const int c0   = blockIdx.x * QB;

    const uint32_t st_base = smb + SM_ST + (uint32_t)grp * 2u * SUB_BYTES;

    // ---- cp.async prologue: subtiles grp*16, grp*16+1 ----
#pragma unroll
    for (int st = 0; st < 2; st++) {
        const char* src = (const char*)&g_B[grp * NSTG + st][0];
        uint32_t dst = st_base + st * SUB_BYTES;
#pragma unroll
        for (int it = 0; it < 4; it++) {
            int off = it * 128 * 16 + gtid * 16;
            CP_ASYNC16(dst + off, src + off);
        }
        CP_COMMIT();
    }

    // ---- pack A fragments: fp16 hi/lo of x[b][k][c0+r] ----
    const float* xb = x + (size_t)b * EMB * CODES + c0;
    for (int p = tid; p < 1024; p += NTHREADS) {
        int ln = p & 31;
        int ks = (p >> 5) & 3;
        int ms = (p >> 7) & 1;
        int w  = p >> 8;
        int r  = w * 32 + ms * 16 + (ln >> 2);
        int c  = ln & 3;
        int k0 = ks * 16 + 2 * c;
        float v00 = xb[(size_t)k0 * CODES + r];
        float v01 = xb[(size_t)(k0 + 1) * CODES + r];
        float v02 = xb[(size_t)(k0 + 8) * CODES + r];
        float v03 = xb[(size_t)(k0 + 9) * CODES + r];
        float v10 = xb[(size_t)k0 * CODES + r + 8];
        float v11 = xb[(size_t)(k0 + 1) * CODES + r + 8];
        float v12 = xb[(size_t)(k0 + 8) * CODES + r + 8];
        float v13 = xb[(size_t)(k0 + 9) * CODES + r + 8];
        uint32_t a0, a1, a2, a3, l0, l1, l2, l3;
        PACKH(a0, v00, v01); PACKH(a1, v10, v11);
        PACKH(a2, v02, v03); PACKH(a3, v12, v13);
        PACKH(l0, lo_res(v00), lo_res(v01)); PACKH(l1, lo_res(v10), lo_res(v11));
        PACKH(l2, lo_res(v02), lo_res(v03)); PACKH(l3, lo_res(v12), lo_res(v13));
        int off = w * 4096 + ms * 2048 + ks * 512 + ln * 16;
        *(uint4*)(sm + SM_A + off)          = make_uint4(a0, a1, a2, a3);
        *(uint4*)(sm + SM_A + 16384 + off)  = make_uint4(l0, l1, l2, l3);
    }
    float* hE2s = (float*)(sm + SM_HE2);
    for (int i = tid; i < NT; i += NTHREADS) hE2s[i] = g_hE2[i];
    __syncthreads();

    float best[4];
    int   bidx[4];
#pragma unroll
    for (int s = 0; s < 4; s++) { best[s] = -3.0e38f; bidx[s] = 0; }

    const uint32_t a0base = smb + SM_A + (uint32_t)mw * 4096u + (uint32_t)lane * 16u;
    const uint32_t a1base = a0base + 16384u;
    const int barid = 1 + grp;
    const uint32_t hlane = smb + SM_HE2 + (uint32_t)(lane & 3) * 8u;

    for (int st = 0; st < NSTG; st++) {
        if (st < NSTG - 2) { CP_WAIT(1); } else { CP_WAIT(0); }
        BARG(barid);

        const uint32_t sb = st_base + (uint32_t)(st & 1) * SUB_BYTES;
        const uint32_t bpair = sb + (uint32_t)lane * 16u;
        float acc[32];
#pragma unroll
        for (int z = 0; z < 32; z++) acc[z] = 0.f;

        STEP(0);
        STEP(1);
        STEP(2);
        STEP(3);

        // ---- epilogue: exact fp32 h-subtract + register argmax ----
        const int tbase = (grp * NSTG + st) * 32;
#pragma unroll
        for (int n = 0; n < 4; n++) {
            int tokb = tbase + n * 8 + (lane & 3) * 2;
            float h0, h1;
            LDS64F(h0, h1, hlane + (uint32_t)(tbase + n * 8) * 4u);
#pragma unroll
            for (int ms = 0; ms < 2; ms++) {
                const float* d = &acc[(ms * 4 + n) * 4];
                float v0 = d[0] - h0;
                float v1 = d[1] - h1;
                float v2 = d[2] - h0;
                float v3 = d[3] - h1;
                int s0 = ms * 2;
                if (v0 > best[s0])     { best[s0] = v0;     bidx[s0] = tokb; }
                if (v1 > best[s0])     { best[s0] = v1;     bidx[s0] = tokb + 1; }
                if (v2 > best[s0 + 1]) { best[s0 + 1] = v2; bidx[s0 + 1] = tokb; }
                if (v3 > best[s0 + 1]) { best[s0 + 1] = v3; bidx[s0 + 1] = tokb + 1; }
            }
        }

        BARG(barid);
        if (st + 2 < NSTG) {
            const char* src = (const char*)&g_B[grp * NSTG + st + 2][0];
            uint32_t dst = st_base + (uint32_t)(st & 1) * SUB_BYTES;
#pragma unroll
            for (int it = 0; it < 4; it++) {
                int off = it * 128 * 16 + gtid * 16;
                CP_ASYNC16(dst + off, src + off);
            }
            CP_COMMIT();
        }
    }

    // ---- merge across the 4 lanes sharing each row ----
#pragma unroll
    for (int s = 0; s < 4; s++) {
#pragma unroll
        for (int off = 1; off <= 2; off <<= 1) {
            float os = __shfl_xor_sync(0xffffffffu, best[s], off);
            int   oi = __shfl_xor_sync(0xffffffffu, bidx[s], off);
            if (os > best[s] || (os == best[s] && oi < bidx[s])) {
                best[s] = os; bidx[s] = oi;
            }
        }
    }

    float* REDS = (float*)(sm + SM_REDS);
    int*   REDI = (int*)(sm + SM_REDI);
    int*   QIDX = (int*)(sm + SM_QIDX);
    if ((lane & 3) == 0) {
#pragma unroll
        for (int s = 0; s < 4; s++) {
            int row = mw * 32 + (s >> 1) * 16 + (lane >> 2) + (s & 1) * 8;
            REDS[row * 2 + grp] = best[s];
            REDI[row * 2 + grp] = bidx[s];
        }
    }
    __syncthreads();

    if (tid < QB) {
        float s0 = REDS[tid * 2], s1 = REDS[tid * 2 + 1];
        int   i0 = REDI[tid * 2], i1 = REDI[tid * 2 + 1];
        int bi = (s1 > s0) ? i1 : i0;   // group0 indices lower; tie -> i0
        QIDX[tid] = bi;
        idxout[(size_t)b * CODES + c0 + tid] = (float)bi;
    }
    __syncthreads();

    // ---- gather x_out ----
#pragma unroll
    for (int it = 0; it < (EMB * QB) / NTHREADS; ++it) {
        int idx = it * NTHREADS + tid;
        int q = idx & (QB - 1);
        int j = idx >> 7;
        xout[(size_t)b * EMB * CODES + (size_t)j * CODES + c0 + q] =
            e[(size_t)QIDX[q] * EMB + j];
    }
}

extern "C" void kernel_launch(void* const* d_in, const int* in_sizes, int n_in,
                              void* d_out, int out_size) {
    const float* x = (const float*)d_in[0];   // [16, 64, 16384]
    const float* e = (const float*)d_in[1];   // [1024, 64]
    int B = in_sizes[0] / (EMB * CODES);

    float* xout   = (float*)d_out;
    float* idxout = xout + (size_t)B * EMB * CODES;

    pre_kernel<<<NSUB, 256>>>(e);

    cudaFuncSetAttribute(vq_kernel, cudaFuncAttributeMaxDynamicSharedMemorySize, SM_TOTAL);
    dim3 grid(CODES / QB, B);
    vq_kernel<<<grid, NTHREADS, SM_TOTAL>>>(x, e, xout, idxout);
}